// round 14
// baseline (speedup 1.0000x reference)
#include <cuda_runtime.h>
#include <cuda_bf16.h>
#include <math.h>

#define T_STEPS 128
#define NE 64
#define NA 8
#define OBS 64
#define D 128
#define CH 128
#define VH 256
#define BATCH 512           // NE*NA
#define TB (T_STEPS*BATCH)  // 65536
#define ITERS 2

// ---------------- scratch (static device arrays: allocation-free) -------------
__device__ float g_gi[TB * 3 * D];
__device__ float g_e[TB * D];
__device__ float g_aiaj[TB * 2 * CH];
__device__ float g_v2[TB * VH];
__device__ unsigned char g_dmask[TB];
__device__ int g_dflag;
__device__ unsigned g_wpk[253952];        // packed weights (hi at off, lo at off+sz)
// packed activations: hi/lo interleaved as [hi block | lo block]
__device__ unsigned g_obsP [2 * TB * 32];
__device__ unsigned g_emb1P[2 * TB * 64];
__device__ unsigned g_emb2P[2 * TB * 64];
__device__ unsigned g_eP   [2 * TB * 64];
__device__ unsigned g_ctxP [2 * TB * 64];
__device__ unsigned g_d1P  [2 * TB * 64];
__device__ unsigned g_v1P  [2 * TB * 128];

#define WPK_TOTAL 126976

// ---------------- dones dtype detection + canonicalization --------------------
__global__ void detect_dones_kernel(const unsigned char* __restrict__ p, int n)
{
    __shared__ int s_nonbin, s_off4;
    if (threadIdx.x == 0) { s_nonbin = 0; s_off4 = 0; }
    __syncthreads();
    int nb = 0, o4 = 0;
    for (int i = threadIdx.x; i < n; i += blockDim.x) {
        const unsigned char b = p[i];
        if (b > 1) nb = 1;
        else if (b == 1 && (i & 3)) o4 = 1;
    }
    if (nb) atomicOr(&s_nonbin, 1);
    if (o4) atomicOr(&s_off4, 1);
    __syncthreads();
    if (threadIdx.x == 0)
        g_dflag = s_nonbin ? 1 : (s_off4 ? 0 : 2);
}

__global__ void conv_dones_kernel(const void* __restrict__ p, int n)
{
    const int i = blockIdx.x * blockDim.x + threadIdx.x;
    if (i >= n) return;
    const int f = g_dflag;
    unsigned char m;
    if (f == 1)      m = (((const float*)p)[i] != 0.f);
    else if (f == 2) m = (((const int*)p)[i] != 0);
    else             m = (((const unsigned char*)p)[i] != 0);
    g_dmask[i] = m;
}

// ---------------- bf16 helpers -------------------------------------------------
__device__ __forceinline__ unsigned pack_bf16(float lo_elem, float hi_elem)
{
    unsigned d;
    asm("cvt.rn.bf16x2.f32 %0, %1, %2;" : "=r"(d) : "f"(hi_elem), "f"(lo_elem));
    return d;
}

__device__ __forceinline__ float bf16hi(float x)
{
    return __bfloat162float(__float2bfloat16(x));
}

// ---------------- one-time weight packing --------------------------------------
__global__ void pack_weights_kernel(
    const float* __restrict__ s0, const float* __restrict__ s1,
    const float* __restrict__ s2, const float* __restrict__ s3,
    const float* __restrict__ s4, const float* __restrict__ s5,
    const float* __restrict__ s6, const float* __restrict__ s7)
{
    const int idx = blockIdx.x * blockDim.x + threadIdx.x;
    if (idx >= WPK_TOTAL) return;
    const int cum[9]  = {0, 4096, 12288, 36864, 53248, 69632, 77824, 94208, 126976};
    const int hoff[8] = {0, 8192, 24576, 73728, 106496, 139264, 155648, 188416};
    const int Ns[8]   = {128, 128, 384, 128, 128, 128, 256, 256};
    int m = 0;
#pragma unroll
    for (int q = 0; q < 7; q++) if (idx >= cum[q + 1]) m = q + 1;
    const float* srcs[8] = {s0, s1, s2, s3, s4, s5, s6, s7};
    const int local = idx - cum[m];
    const int N = Ns[m];
    const int kp = local / N;
    const int n  = local - kp * N;
    const float* S = srcs[m];
    const float v0 = S[(size_t)(2 * kp) * N + n];
    const float v1 = S[(size_t)(2 * kp + 1) * N + n];
    const float h0 = bf16hi(v0), h1 = bf16hi(v1);
    const int sz = cum[m + 1] - cum[m];
    g_wpk[hoff[m] + local]      = pack_bf16(h0, h1);
    g_wpk[hoff[m] + sz + local] = pack_bf16(v0 - h0, v1 - h1);
}

// ---------------- activation packing (obs, once per launch) --------------------
__global__ void pack_act_kernel(const float* __restrict__ src,
                                unsigned* __restrict__ dh, unsigned* __restrict__ dl,
                                int total, int Kp)
{
    const int idx = blockIdx.x * blockDim.x + threadIdx.x;
    if (idx >= total) return;
    const int m = idx / Kp, kp = idx - m * Kp;
    const float v0 = src[(size_t)m * 2 * Kp + 2 * kp];
    const float v1 = src[(size_t)m * 2 * Kp + 2 * kp + 1];
    const float h0 = bf16hi(v0), h1 = bf16hi(v1);
    dh[idx] = pack_bf16(h0, h1);
    dl[idx] = pack_bf16(v0 - h0, v1 - h1);
}

// ---------------- BF16 GEMM: all-packed operands, 4-stage cp.async -------------
// flags: 1 relu | 2 dual-A | 4 resid+alive | 8 B column-split
#define BM 128
#define BN 128
#define AST 12
#define BST 136
#define STG 4
#define A_ST_U32 (BM*AST)        // 1536 per hi/lo
#define B_ST_U32 (8*BST)         // 1088 per hi/lo
#define SMEM_TG ((STG*2*A_ST_U32 + STG*2*B_ST_U32) * 4)   // 83968 B

__device__ __forceinline__ void mma_bf16(float* c, const unsigned* a, const unsigned* b)
{
    asm volatile(
        "mma.sync.aligned.m16n8k16.row.col.f32.bf16.bf16.f32 "
        "{%0,%1,%2,%3}, {%4,%5,%6,%7}, {%8,%9}, {%0,%1,%2,%3};"
        : "+f"(c[0]), "+f"(c[1]), "+f"(c[2]), "+f"(c[3])
        : "r"(a[0]), "r"(a[1]), "r"(a[2]), "r"(a[3]), "r"(b[0]), "r"(b[1]));
}

__device__ __forceinline__ void ldsm_x4(unsigned& r0, unsigned& r1, unsigned& r2,
                                        unsigned& r3, unsigned addr)
{
    asm volatile("ldmatrix.sync.aligned.m8n8.x4.shared.b16 {%0,%1,%2,%3}, [%4];"
                 : "=r"(r0), "=r"(r1), "=r"(r2), "=r"(r3) : "r"(addr));
}

__device__ __forceinline__ void cp16(unsigned dst, const unsigned* src)
{
    asm volatile("cp.async.cg.shared.global [%0], [%1], 16;" :: "r"(dst), "l"(src));
}

__global__ __launch_bounds__(256, 2) void tgemm_kernel(
    int M, int N, int tilesPerSrc, int ldaP, int ldbP,
    const unsigned* __restrict__ Aph, const unsigned* __restrict__ Apl,
    const unsigned* __restrict__ A2h, const unsigned* __restrict__ A2l,
    const unsigned* __restrict__ Bmh, const unsigned* __restrict__ Bml,
    const unsigned* __restrict__ B2h, const unsigned* __restrict__ B2l,
    const float* __restrict__ bias,
    float* __restrict__ CoutF,
    unsigned* __restrict__ CPh, unsigned* __restrict__ CPl,
    int flags, const float* __restrict__ Ein,
    const unsigned char* __restrict__ dones)
{
    extern __shared__ unsigned smu[];
    unsigned* BsBase = smu + STG * 2 * A_ST_U32;
    const unsigned smA = (unsigned)__cvta_generic_to_shared(smu);
    const unsigned smB = (unsigned)__cvta_generic_to_shared(BsBase);

    const int tid  = threadIdx.x;
    const int brow = blockIdx.y * BM;
    const int bcol = blockIdx.x * BN;
    const int w    = tid >> 5, lane = tid & 31;
    const int gid  = lane >> 2, tig = lane & 3;
    const int wm   = (w & 1) * 64;
    const int wn   = (w >> 1) * 32;

    const unsigned laneOff = ((wm + (lane & 15)) * AST + ((lane & 16) >> 2)) * 4;

    // copy-thread mapping
    const int arow = tid >> 1, ac = (tid & 1) * 4;     // A: 128 rows x 2 chunks
    const int bkp  = tid >> 5, bcl = (tid & 31) * 4;   // B: 8 kp-rows x 32 cols

    float acc[4][4][4];
#pragma unroll
    for (int i = 0; i < 4; i++)
#pragma unroll
        for (int j = 0; j < 4; j++)
#pragma unroll
            for (int q = 0; q < 4; q++) acc[i][j][q] = 0.f;

    const int nsrc = (flags & 2) ? 2 : 1;
    const int ntiles = nsrc * tilesPerSrc;

    auto issue_tile = [&](int t) {
        const int s   = (t >= tilesPerSrc) ? 1 : 0;
        const int kp0 = (t - s * tilesPerSrc) * 8;
        const unsigned* aph = s ? A2h : Aph;
        const unsigned* apl = s ? A2l : Apl;
        const unsigned *bph, *bpl;
        int bc;
        if (flags & 8) {
            const bool hi = (bcol >= BN);
            bph = hi ? B2h : Bmh;  bpl = hi ? B2l : Bml;  bc = 0;
        } else {
            bph = s ? B2h : Bmh;   bpl = s ? B2l : Bml;   bc = bcol;
        }
        const int st = t & (STG - 1);
        const unsigned dA = smA + (st * 2 * A_ST_U32 + arow * AST + ac) * 4;
        const size_t aoff = (size_t)(brow + arow) * ldaP + kp0 + ac;
        cp16(dA, aph + aoff);
        cp16(dA + A_ST_U32 * 4, apl + aoff);
        const unsigned dB = smB + (st * 2 * B_ST_U32 + bkp * BST + bcl) * 4;
        const size_t boff = (size_t)(kp0 + bkp) * ldbP + bc + bcl;
        cp16(dB, bph + boff);
        cp16(dB + B_ST_U32 * 4, bpl + boff);
        asm volatile("cp.async.commit_group;" ::: "memory");
    };

    issue_tile(0);
    issue_tile(1);
    issue_tile(2);

    for (int t = 0; t < ntiles; t++) {
        asm volatile("cp.async.wait_group 2;" ::: "memory");
        __syncthreads();
        if (t + 3 < ntiles) issue_tile(t + 3);
        else asm volatile("cp.async.commit_group;" ::: "memory");

        const int st = t & (STG - 1);
        const unsigned* Bsh = BsBase + st * 2 * B_ST_U32;
        const unsigned* Bsl = Bsh + B_ST_U32;
        const unsigned aTileH = smA + (unsigned)(st * 2 * A_ST_U32 * 4) + laneOff;
        const unsigned aTileL = aTileH + (unsigned)(A_ST_U32 * 4);

        unsigned bh[4][2], bl[4][2];
#pragma unroll
        for (int ns = 0; ns < 4; ns++) {
            const int n = wn + ns * 8 + gid;
            bh[ns][0] = Bsh[tig * BST + n];
            bh[ns][1] = Bsh[(tig + 4) * BST + n];
            bl[ns][0] = Bsl[tig * BST + n];
            bl[ns][1] = Bsl[(tig + 4) * BST + n];
        }
#pragma unroll
        for (int ms = 0; ms < 4; ms++) {
            unsigned ah[4], al[4];
            ldsm_x4(ah[0], ah[1], ah[2], ah[3], aTileH + (unsigned)(ms * 16 * AST * 4));
            ldsm_x4(al[0], al[1], al[2], al[3], aTileL + (unsigned)(ms * 16 * AST * 4));
#pragma unroll
            for (int ns = 0; ns < 4; ns++) {
                mma_bf16(acc[ms][ns], ah, bh[ns]);
                mma_bf16(acc[ms][ns], ah, bl[ns]);
                mma_bf16(acc[ms][ns], al, bh[ns]);
            }
        }
    }

    const bool hasb   = (bias != nullptr);
    const bool resid  = (flags & 4);
    const bool dorelu = (flags & 5);
    const int  Np     = N >> 1;
#pragma unroll
    for (int ms = 0; ms < 4; ms++) {
        const int r0 = brow + wm + ms * 16 + gid;
        const int r1 = r0 + 8;
        float alive0 = 1.f, alive1 = 1.f;
        const float *E0 = nullptr, *E1 = nullptr;
        if (resid) {
            alive0 = dones[r0] ? 0.f : 1.f;
            alive1 = dones[r1] ? 0.f : 1.f;
            E0 = Ein + (size_t)r0 * N;
            E1 = Ein + (size_t)r1 * N;
        }
#pragma unroll
        for (int ns = 0; ns < 4; ns++) {
            const int c = bcol + wn + ns * 8 + tig * 2;
            float b0 = 0.f, b1 = 0.f;
            if (hasb) { b0 = bias[c]; b1 = bias[c + 1]; }
            float v0 = acc[ms][ns][0] + b0;
            float v1 = acc[ms][ns][1] + b1;
            float v2 = acc[ms][ns][2] + b0;
            float v3 = acc[ms][ns][3] + b1;
            if (dorelu) {
                v0 = fmaxf(v0, 0.f); v1 = fmaxf(v1, 0.f);
                v2 = fmaxf(v2, 0.f); v3 = fmaxf(v3, 0.f);
            }
            if (resid) {
                v0 = (E0[c] + v0) * alive0;     v1 = (E0[c + 1] + v1) * alive0;
                v2 = (E1[c] + v2) * alive1;     v3 = (E1[c + 1] + v3) * alive1;
            }
            if (CoutF) {
                *(float2*)&CoutF[(size_t)r0 * N + c] = make_float2(v0, v1);
                *(float2*)&CoutF[(size_t)r1 * N + c] = make_float2(v2, v3);
            }
            if (CPh) {
                const size_t i0 = (size_t)r0 * Np + (c >> 1);
                const size_t i1 = (size_t)r1 * Np + (c >> 1);
                float h0 = bf16hi(v0), h1 = bf16hi(v1);
                CPh[i0] = pack_bf16(h0, h1);
                CPl[i0] = pack_bf16(v0 - h0, v1 - h1);
                h0 = bf16hi(v2); h1 = bf16hi(v3);
                CPh[i1] = pack_bf16(h0, h1);
                CPl[i1] = pack_bf16(v2 - h0, v3 - h1);
            }
        }
    }
}

// ---------------- persistent GRU scan (fp32 + packed e out) --------------------
#define RPB 4
#define GTH 384

__device__ __forceinline__ unsigned long long fma_f32x2(
    unsigned long long a, unsigned long long b, unsigned long long c)
{
    unsigned long long d;
    asm("fma.rn.f32x2 %0, %1, %2, %3;" : "=l"(d) : "l"(a), "l"(b), "l"(c));
    return d;
}

__device__ __forceinline__ float sig_fast(float x)
{
    return __fdividef(1.f, 1.f + __expf(-x));
}
__device__ __forceinline__ float tanh_fast(float x)
{
    return __fdividef(2.f, 1.f + __expf(-2.f * x)) - 1.f;
}

__global__ __launch_bounds__(GTH, 1) void gru_kernel(
    const float* __restrict__ gi,
    const unsigned char* __restrict__ dones,
    const float* __restrict__ h0,
    const float* __restrict__ Wh,
    const float* __restrict__ bhn,
    float* __restrict__ e_out,
    unsigned* __restrict__ eph, unsigned* __restrict__ epl,
    float* __restrict__ hidden_out)
{
    __shared__ __align__(16) float hs2[64 * 8];
    __shared__ float ghs[RPB * 384];
    __shared__ float sbhn[D];
    __shared__ unsigned char sdn[T_STEPS * RPB];

    const int tid = threadIdx.x;
    const int rowbase = blockIdx.x * RPB;

    unsigned long long w[64];
#pragma unroll
    for (int kp = 0; kp < 64; kp++) {
        const unsigned lo = __float_as_uint(Wh[(size_t)(2 * kp) * 384 + tid]);
        const unsigned hi = __float_as_uint(Wh[(size_t)(2 * kp + 1) * 384 + tid]);
        w[kp] = ((unsigned long long)hi << 32) | lo;
    }
    if (tid < D) sbhn[tid] = bhn[tid];
    if (tid < T_STEPS)
        *(uchar4*)&sdn[tid * 4] = *(const uchar4*)&dones[tid * BATCH + rowbase];

    const int rA = tid >> 7, dA = tid & 127;
    const int rowA = rowbase + rA;
    const bool hasB = (tid < 128);
    const int rowB = rowbase + 3;

    float pa0, pa1, pa2, pb0 = 0.f, pb1 = 0.f, pb2 = 0.f;
    auto prefetch = [&](int t) {
        const size_t gibA = ((size_t)t * BATCH + rowA) * (3 * D);
        pa0 = gi[gibA + dA];
        pa1 = gi[gibA + D + dA];
        pa2 = gi[gibA + 2 * D + dA];
        if (hasB) {
            const size_t gibB = ((size_t)t * BATCH + rowB) * (3 * D);
            pb0 = gi[gibB + tid];
            pb1 = gi[gibB + D + tid];
            pb2 = gi[gibB + 2 * D + tid];
        }
    };

    prefetch(0);
    __syncthreads();

    for (int idx = tid; idx < RPB * D; idx += GTH) {
        const int r = idx >> 7, d = idx & 127;
        const int row = rowbase + r;
        float v = sdn[r] ? 0.f : h0[(size_t)row * D + d];
        hs2[(d >> 1) * 8 + r * 2 + (d & 1)] = v;
    }
    __syncthreads();

    for (int t = 0; t < T_STEPS; t++) {
        {
            unsigned long long a0 = 0, a1 = 0, a2 = 0, a3 = 0;
#pragma unroll
            for (int kp = 0; kp < 64; kp++) {
                const ulonglong2 p01 = *(const ulonglong2*)(hs2 + kp * 8);
                const ulonglong2 p23 = *(const ulonglong2*)(hs2 + kp * 8 + 4);
                a0 = fma_f32x2(w[kp], p01.x, a0);
                a1 = fma_f32x2(w[kp], p01.y, a1);
                a2 = fma_f32x2(w[kp], p23.x, a2);
                a3 = fma_f32x2(w[kp], p23.y, a3);
            }
            ghs[0 * 384 + tid] = __uint_as_float((unsigned)a0) + __uint_as_float((unsigned)(a0 >> 32));
            ghs[1 * 384 + tid] = __uint_as_float((unsigned)a1) + __uint_as_float((unsigned)(a1 >> 32));
            ghs[2 * 384 + tid] = __uint_as_float((unsigned)a2) + __uint_as_float((unsigned)(a2 >> 32));
            ghs[3 * 384 + tid] = __uint_as_float((unsigned)a3) + __uint_as_float((unsigned)(a3 >> 32));
        }
        __syncthreads();

        {
            {
                const int r = rA, d = dA, row = rowA;
                const float h_r = ghs[r * 384 + d];
                const float h_z = ghs[r * 384 + D + d];
                const float h_n = ghs[r * 384 + 2 * D + d];
                const int hsidx = (d >> 1) * 8 + r * 2 + (d & 1);
                const float hprev = hs2[hsidx];
                const float rg = sig_fast(pa0 + h_r);
                const float zg = sig_fast(pa1 + h_z);
                const float ng = tanh_fast(pa2 + rg * (h_n + sbhn[d]));
                const float hn = (1.f - zg) * ng + zg * hprev;
                const float ev = sdn[t * 4 + r] ? 0.f : hn;
                const size_t mrow = (size_t)t * BATCH + row;
                e_out[mrow * D + d] = ev;
                const float evo = __shfl_down_sync(0xffffffffu, ev, 1);
                if (!(d & 1)) {
                    const float h0p = bf16hi(ev), h1p = bf16hi(evo);
                    eph[mrow * 64 + (d >> 1)] = pack_bf16(h0p, h1p);
                    epl[mrow * 64 + (d >> 1)] = pack_bf16(ev - h0p, evo - h1p);
                }
                if (t == T_STEPS - 1) hidden_out[(size_t)row * D + d] = hn;
                else hs2[hsidx] = sdn[(t + 1) * 4 + r] ? 0.f : hn;
            }
            if (hasB) {
                const int d = tid, row = rowB;
                const float h_r = ghs[3 * 384 + d];
                const float h_z = ghs[3 * 384 + D + d];
                const float h_n = ghs[3 * 384 + 2 * D + d];
                const int hsidx = (d >> 1) * 8 + 3 * 2 + (d & 1);
                const float hprev = hs2[hsidx];
                const float rg = sig_fast(pb0 + h_r);
                const float zg = sig_fast(pb1 + h_z);
                const float ng = tanh_fast(pb2 + rg * (h_n + sbhn[d]));
                const float hn = (1.f - zg) * ng + zg * hprev;
                const float ev = sdn[t * 4 + 3] ? 0.f : hn;
                const size_t mrow = (size_t)t * BATCH + row;
                e_out[mrow * D + d] = ev;
                const float evo = __shfl_down_sync(0xffffffffu, ev, 1);
                if (!(d & 1)) {
                    const float h0p = bf16hi(ev), h1p = bf16hi(evo);
                    eph[mrow * 64 + (d >> 1)] = pack_bf16(h0p, h1p);
                    epl[mrow * 64 + (d >> 1)] = pack_bf16(ev - h0p, evo - h1p);
                }
                if (t == T_STEPS - 1) hidden_out[(size_t)row * D + d] = hn;
                else hs2[hsidx] = sdn[(t + 1) * 4 + 3] ? 0.f : hn;
            }
        }
        if (t + 1 < T_STEPS) prefetch(t + 1);
        __syncthreads();
    }
}

// ---------------- fused pairwise-coupling C + context (packed ctx out) ---------
__global__ __launch_bounds__(256) void couple_ctx_kernel(
    const float* __restrict__ e, const float* __restrict__ aiaj,
    const float* __restrict__ chb,
    const float* __restrict__ cow, const float* __restrict__ cob,
    unsigned* __restrict__ ctxPh, unsigned* __restrict__ ctxPl)
{
    __shared__ float sai[NA * 132];
    __shared__ float sajt[128 * 9];
    __shared__ float se[NA * D];
    __shared__ float sb[CH], sw[CH];
    __shared__ float sC[NA * NA];

    const int g  = blockIdx.x;
    const size_t base  = (size_t)g * NA * D;
    const size_t base2 = (size_t)g * NA * 256;
    const int tid = threadIdx.x;
    const int lane = tid & 31, warp = tid >> 5;

    {
        const int j = warp;
        const int k0 = lane * 4;
        const float4 vi = *(const float4*)&aiaj[base2 + j * 256 + k0];
        const float4 vj = *(const float4*)&aiaj[base2 + j * 256 + 128 + k0];
        *(float4*)&sai[j * 132 + k0] = vi;
        sajt[(k0 + 0) * 9 + j] = vj.x;
        sajt[(k0 + 1) * 9 + j] = vj.y;
        sajt[(k0 + 2) * 9 + j] = vj.z;
        sajt[(k0 + 3) * 9 + j] = vj.w;
    }
    *(float4*)&se[tid * 4] = *(const float4*)&e[base + tid * 4];
    if (tid < CH) { sb[tid] = chb[tid]; sw[tid] = cow[tid]; }
    __syncthreads();

    {
        const int i = warp;
        const int jj = lane & 7, slice = lane >> 3;
        const float cb = cob[0];
        float s = 0.f;
#pragma unroll
        for (int it = 0; it < 32; it++) {
            const int kk = slice * 32 + ((it + slice * 8) & 31);
            const float v = sai[i * 132 + kk] + sajt[kk * 9 + jj] + sb[kk];
            s += fmaxf(v, 0.f) * sw[kk];
        }
        s += __shfl_xor_sync(0xffffffffu, s, 8);
        s += __shfl_xor_sync(0xffffffffu, s, 16);
        if (lane < 8)
            sC[i * NA + lane] = (i == lane) ? 0.f : 1.f / (1.f + expf(-(s + cb)));
    }
    __syncthreads();

#pragma unroll
    for (int q = 0; q < 4; q++) {
        const int idx = tid + q * 256;
        const int i = idx >> 7, d = idx & 127;
        float s = 0.f;
#pragma unroll
        for (int j = 0; j < NA; j++) s += sC[i * NA + j] * se[j * D + d];
        const float so = __shfl_down_sync(0xffffffffu, s, 1);
        if (!(d & 1)) {
            const float h0 = bf16hi(s), h1 = bf16hi(so);
            const size_t o = (size_t)(g * NA + i) * 64 + (d >> 1);
            ctxPh[o] = pack_bf16(h0, h1);
            ctxPl[o] = pack_bf16(s - h0, so - h1);
        }
    }
}

// ---------------- final value projection (VH -> 1) ------------------------------
__global__ __launch_bounds__(256) void vout_kernel(
    const float* __restrict__ v2, const float* __restrict__ w,
    const float* __restrict__ b, float* __restrict__ out)
{
    __shared__ float sw[VH];
    const int tid = threadIdx.x;
    sw[tid] = w[tid];
    __syncthreads();
    const int warp = tid >> 5, lane = tid & 31;
    const int row = blockIdx.x * 8 + warp;
    const float* vp = v2 + (size_t)row * VH;
    float s = 0.f;
#pragma unroll
    for (int k = lane; k < VH; k += 32) s += vp[k] * sw[k];
#pragma unroll
    for (int off = 16; off; off >>= 1) s += __shfl_xor_sync(0xffffffffu, s, off);
    if (lane == 0) out[row] = s + b[0];
}

// ---------------- launcher -------------------------------------------------------
extern "C" void kernel_launch(void* const* d_in, const int* in_sizes, int n_in,
                              void* d_out, int out_size)
{
    const float* hidden = (const float*)d_in[0];
    const float* obs    = (const float*)d_in[1];
    const void*  dones_raw = d_in[2];
    const float* e1w = (const float*)d_in[3];
    const float* e1b = (const float*)d_in[4];
    const float* e2w = (const float*)d_in[5];
    const float* e2b = (const float*)d_in[6];
    const float* gWi = (const float*)d_in[7];
    const float* gbi = (const float*)d_in[8];
    const float* gWh = (const float*)d_in[9];
    const float* gbhn = (const float*)d_in[10];
    const float* chw = (const float*)d_in[11];
    const float* chb = (const float*)d_in[12];
    const float* cow = (const float*)d_in[13];
    const float* cob = (const float*)d_in[14];
    const float* uhw = (const float*)d_in[15];
    const float* uhb = (const float*)d_in[16];
    const float* uow = (const float*)d_in[17];
    const float* uob = (const float*)d_in[18];
    const float* v1w = (const float*)d_in[19];
    const float* v1b = (const float*)d_in[20];
    const float* v2w = (const float*)d_in[21];
    const float* v2b = (const float*)d_in[22];
    const float* vow = (const float*)d_in[23];
    const float* vob = (const float*)d_in[24];

    float* out_hidden = (float*)d_out;                 // (B, D)
    float* out_values = (float*)d_out + BATCH * D;     // (T, B)

    float *gi, *e, *aiaj, *v2;
    unsigned char* dmask;
    unsigned *wpk, *obsP, *emb1P, *emb2P, *eP, *ctxP, *d1P, *v1P;
    cudaGetSymbolAddress((void**)&gi,    g_gi);
    cudaGetSymbolAddress((void**)&e,     g_e);
    cudaGetSymbolAddress((void**)&aiaj,  g_aiaj);
    cudaGetSymbolAddress((void**)&v2,    g_v2);
    cudaGetSymbolAddress((void**)&dmask, g_dmask);
    cudaGetSymbolAddress((void**)&wpk,   g_wpk);
    cudaGetSymbolAddress((void**)&obsP,  g_obsP);
    cudaGetSymbolAddress((void**)&emb1P, g_emb1P);
    cudaGetSymbolAddress((void**)&emb2P, g_emb2P);
    cudaGetSymbolAddress((void**)&eP,    g_eP);
    cudaGetSymbolAddress((void**)&ctxP,  g_ctxP);
    cudaGetSymbolAddress((void**)&d1P,   g_d1P);
    cudaGetSymbolAddress((void**)&v1P,   g_v1P);

    // hi/lo pointer pairs (lo = hi + block size)
    unsigned *obsPh = obsP,   *obsPl = obsP  + (size_t)TB * 32;
    unsigned *e1Ph  = emb1P,  *e1Pl  = emb1P + (size_t)TB * 64;
    unsigned *e2Ph  = emb2P,  *e2Pl  = emb2P + (size_t)TB * 64;
    unsigned *ePh   = eP,     *ePl   = eP    + (size_t)TB * 64;
    unsigned *ctxh  = ctxP,   *ctxl  = ctxP  + (size_t)TB * 64;
    unsigned *d1h   = d1P,    *d1l   = d1P   + (size_t)TB * 64;
    unsigned *v1h   = v1P,    *v1l   = v1P   + (size_t)TB * 128;

    unsigned* e1wP = wpk + 0;        // sz 4096
    unsigned* e2wP = wpk + 8192;     // sz 8192
    unsigned* gWiP = wpk + 24576;    // sz 24576
    unsigned* chwP = wpk + 73728;    // sz 16384
    unsigned* uhwP = wpk + 106496;   // sz 16384
    unsigned* uowP = wpk + 139264;   // sz 8192
    unsigned* v1wP = wpk + 155648;   // sz 16384
    unsigned* v2wP = wpk + 188416;   // sz 32768

    cudaFuncSetAttribute(tgemm_kernel, cudaFuncAttributeMaxDynamicSharedMemorySize, SMEM_TG);

    const int M = TB;
    const dim3 blk(256);

    detect_dones_kernel<<<1, 256>>>((const unsigned char*)dones_raw, TB);
    conv_dones_kernel<<<TB / 256, 256>>>(dones_raw, TB);
    pack_weights_kernel<<<(WPK_TOTAL + 255) / 256, 256>>>(
        e1w, e2w, gWi, chw, uhw, uow, v1w, v2w);
    pack_act_kernel<<<(TB * 32 + 255) / 256, 256>>>(obs, obsPh, obsPl, TB * 32, 32);

    // embed1: relu(obs @ e1w + e1b) -> packed
    tgemm_kernel<<<dim3(1, M / BM), blk, SMEM_TG>>>(M, D, 4, 32, 128,
        obsPh, obsPl, nullptr, nullptr, e1wP, e1wP + 4096, nullptr, nullptr,
        e1b, nullptr, e1Ph, e1Pl, 1, nullptr, nullptr);
    // embed2 -> packed
    tgemm_kernel<<<dim3(1, M / BM), blk, SMEM_TG>>>(M, D, 8, 64, 128,
        e1Ph, e1Pl, nullptr, nullptr, e2wP, e2wP + 8192, nullptr, nullptr,
        e2b, nullptr, e2Ph, e2Pl, 1, nullptr, nullptr);
    // gi -> fp32
    tgemm_kernel<<<dim3(3, M / BM), blk, SMEM_TG>>>(M, 3 * D, 8, 64, 3 * D,
        e2Ph, e2Pl, nullptr, nullptr, gWiP, gWiP + 24576, nullptr, nullptr,
        gbi, gi, nullptr, nullptr, 0, nullptr, nullptr);
    // GRU -> e fp32 + packed
    gru_kernel<<<BATCH / RPB, GTH>>>(gi, dmask, hidden, gWh, gbhn, e, ePh, ePl, out_hidden);

    for (int it = 0; it < ITERS; it++) {
        // [ai|aj] = e @ [W1|W2] -> fp32 (couple input)
        tgemm_kernel<<<dim3(2, M / BM), blk, SMEM_TG>>>(M, 2 * CH, 8, 64, CH,
            ePh, ePl, nullptr, nullptr,
            chwP, chwP + 16384, chwP + 8192, chwP + 16384 + 8192,
            nullptr, aiaj, nullptr, nullptr, 8, nullptr, nullptr);
        couple_ctx_kernel<<<T_STEPS * NE, 256>>>(e, aiaj, chb, cow, cob, ctxh, ctxl);
        // d1 = relu(e@U1 + ctx@U2 + uhb) -> packed
        tgemm_kernel<<<dim3(1, M / BM), blk, SMEM_TG>>>(M, D, 8, 64, D,
            ePh, ePl, ctxh, ctxl,
            uhwP, uhwP + 16384, uhwP + 8192, uhwP + 16384 + 8192,
            uhb, nullptr, d1h, d1l, 1 | 2, nullptr, nullptr);
        // e = (e + relu(d1@uow + uob)) * alive -> fp32 + packed
        tgemm_kernel<<<dim3(1, M / BM), blk, SMEM_TG>>>(M, D, 8, 64, D,
            d1h, d1l, nullptr, nullptr, uowP, uowP + 8192, nullptr, nullptr,
            uob, e, ePh, ePl, 4, e, dmask);
    }

    // value head
    tgemm_kernel<<<dim3(2, M / BM), blk, SMEM_TG>>>(M, VH, 8, 64, VH,
        ePh, ePl, nullptr, nullptr, v1wP, v1wP + 16384, nullptr, nullptr,
        v1b, nullptr, v1h, v1l, 1, nullptr, nullptr);
    tgemm_kernel<<<dim3(2, M / BM), blk, SMEM_TG>>>(M, VH, 16, 128, VH,
        v1h, v1l, nullptr, nullptr, v2wP, v2wP + 32768, nullptr, nullptr,
        v2b, v2, nullptr, nullptr, 1, nullptr, nullptr);
    vout_kernel<<<TB / 8, 256>>>(v2, vow, vob, out_values);
}

// round 15
// speedup vs baseline: 1.0038x; 1.0038x over previous
#include <cuda_runtime.h>
#include <cuda_bf16.h>
#include <math.h>

#define T_STEPS 128
#define NE 64
#define NA 8
#define OBS 64
#define D 128
#define CH 128
#define VH 256
#define BATCH 512           // NE*NA
#define TB (T_STEPS*BATCH)  // 65536
#define ITERS 2

// ---------------- scratch (static device arrays: allocation-free) -------------
__device__ float g_emb1[TB * D];
__device__ float g_emb2[TB * D];
__device__ float g_gi[TB * 3 * D];
__device__ float g_e[TB * D];
__device__ float g_aiaj[TB * 2 * CH];
__device__ float g_ctx[TB * D];
__device__ float g_d1[TB * D];
__device__ float g_v1[TB * VH];
__device__ unsigned char g_dmask[TB];
__device__ int g_dflag;
__device__ unsigned g_wpk[253952];      // packed bf16 hi/lo weights (u32)
#define WPK_TOTAL 126976

// ---------------- dones dtype detection + canonicalization --------------------
__global__ void detect_dones_kernel(const unsigned char* __restrict__ p, int n)
{
    __shared__ int s_nonbin, s_off4;
    if (threadIdx.x == 0) { s_nonbin = 0; s_off4 = 0; }
    __syncthreads();
    int nb = 0, o4 = 0;
    for (int i = threadIdx.x; i < n; i += blockDim.x) {
        const unsigned char b = p[i];
        if (b > 1) nb = 1;
        else if (b == 1 && (i & 3)) o4 = 1;
    }
    if (nb) atomicOr(&s_nonbin, 1);
    if (o4) atomicOr(&s_off4, 1);
    __syncthreads();
    if (threadIdx.x == 0)
        g_dflag = s_nonbin ? 1 : (s_off4 ? 0 : 2);
}

__global__ void conv_dones_kernel(const void* __restrict__ p, int n)
{
    const int i = blockIdx.x * blockDim.x + threadIdx.x;
    if (i >= n) return;
    const int f = g_dflag;
    unsigned char m;
    if (f == 1)      m = (((const float*)p)[i] != 0.f);
    else if (f == 2) m = (((const int*)p)[i] != 0);
    else             m = (((const unsigned char*)p)[i] != 0);
    g_dmask[i] = m;
}

// ---------------- bf16 helpers -------------------------------------------------
__device__ __forceinline__ unsigned pack_bf16(float lo_elem, float hi_elem)
{
    unsigned d;
    asm("cvt.rn.bf16x2.f32 %0, %1, %2;" : "=r"(d) : "f"(hi_elem), "f"(lo_elem));
    return d;
}

__device__ __forceinline__ float bf16hi(float x)
{
    return __bfloat162float(__float2bfloat16(x));
}

// ---------------- one-time weight packing --------------------------------------
__global__ void pack_weights_kernel(
    const float* __restrict__ s0, const float* __restrict__ s1,
    const float* __restrict__ s2, const float* __restrict__ s3,
    const float* __restrict__ s4, const float* __restrict__ s5,
    const float* __restrict__ s6, const float* __restrict__ s7)
{
    const int idx = blockIdx.x * blockDim.x + threadIdx.x;
    if (idx >= WPK_TOTAL) return;
    const int cum[9]  = {0, 4096, 12288, 36864, 53248, 69632, 77824, 94208, 126976};
    const int hoff[8] = {0, 8192, 24576, 73728, 106496, 139264, 155648, 188416};
    const int Ns[8]   = {128, 128, 384, 128, 128, 128, 256, 256};
    int m = 0;
#pragma unroll
    for (int q = 0; q < 7; q++) if (idx >= cum[q + 1]) m = q + 1;
    const float* srcs[8] = {s0, s1, s2, s3, s4, s5, s6, s7};
    const int local = idx - cum[m];
    const int N = Ns[m];
    const int kp = local / N;
    const int n  = local - kp * N;
    const float* S = srcs[m];
    const float v0 = S[(size_t)(2 * kp) * N + n];
    const float v1 = S[(size_t)(2 * kp + 1) * N + n];
    const float h0 = bf16hi(v0), h1 = bf16hi(v1);
    const int sz = cum[m + 1] - cum[m];
    g_wpk[hoff[m] + local]      = pack_bf16(h0, h1);
    g_wpk[hoff[m] + sz + local] = pack_bf16(v0 - h0, v1 - h1);
}

// ---------------- init values buffer -------------------------------------------
__global__ void init_values_kernel(float* __restrict__ out, const float* __restrict__ b)
{
    out[blockIdx.x * blockDim.x + threadIdx.x] = b[0];
}

// ---------------- BF16 tensor-core GEMM (pre-packed weights) -------------------
// flags: 1 relu | 2 dual-source | 4 resid+alive | 8 B column-split | 16 fused vout
#define BM 128
#define BN 128
#define BK 16
#define AST 12
#define BST 136

__device__ __forceinline__ void mma_bf16(float* c, const unsigned* a, const unsigned* b)
{
    asm volatile(
        "mma.sync.aligned.m16n8k16.row.col.f32.bf16.bf16.f32 "
        "{%0,%1,%2,%3}, {%4,%5,%6,%7}, {%8,%9}, {%0,%1,%2,%3};"
        : "+f"(c[0]), "+f"(c[1]), "+f"(c[2]), "+f"(c[3])
        : "r"(a[0]), "r"(a[1]), "r"(a[2]), "r"(a[3]), "r"(b[0]), "r"(b[1]));
}

__device__ __forceinline__ void ldsm_x4(unsigned& r0, unsigned& r1, unsigned& r2,
                                        unsigned& r3, unsigned addr)
{
    asm volatile("ldmatrix.sync.aligned.m8n8.x4.shared.b16 {%0,%1,%2,%3}, [%4];"
                 : "=r"(r0), "=r"(r1), "=r"(r2), "=r"(r3) : "r"(addr));
}

__global__ __launch_bounds__(256) void tgemm_kernel(
    int M, int N, int K, int ldb,
    const float* __restrict__ A, const float* __restrict__ A2,
    const unsigned* __restrict__ Bmh, const unsigned* __restrict__ Bml,
    const unsigned* __restrict__ B2h, const unsigned* __restrict__ B2l,
    const float* __restrict__ bias, float* __restrict__ Cout,
    int flags, const float* __restrict__ Ein,
    const unsigned char* __restrict__ dones,
    const float* __restrict__ vw)
{
    __shared__ __align__(16) unsigned As[2][2][BM * AST];
    __shared__ __align__(16) unsigned Bs[2][2][(BK / 2) * BST];

    const int tid  = threadIdx.x;
    const int brow = blockIdx.y * BM;
    const int bcol = blockIdx.x * BN;
    const int w    = tid >> 5, lane = tid & 31;
    const int gid  = lane >> 2, tig = lane & 3;
    const int wm   = (w & 1) * 64;
    const int wn   = (w >> 1) * 32;

    const int arow0 = tid >> 2;
    const int brw   = tid >> 5;
    const int bfc   = (tid & 31) * 4;

    const unsigned aSmemBase = (unsigned)__cvta_generic_to_shared(&As[0][0][0]);
    const unsigned laneOff = ((wm + (lane & 15)) * AST + ((lane & 16) >> 2)) * 4;

    float acc[4][4][4];
#pragma unroll
    for (int i = 0; i < 4; i++)
#pragma unroll
        for (int j = 0; j < 4; j++)
#pragma unroll
            for (int q = 0; q < 4; q++) acc[i][j][q] = 0.f;

    const int nsrc = (flags & 2) ? 2 : 1;
    const int tilesPerSrc = K / BK;
    const int ntiles = nsrc * tilesPerSrc;

    float4 rA[2];
    uint4 rBh, rBl;

    auto loadTile = [&](int t) {
        const int s  = (t >= tilesPerSrc) ? 1 : 0;
        const int k0 = (t - s * tilesPerSrc) * BK;
        const float* Ap = s ? A2 : A;
        const unsigned *Bph, *Bpl;
        int bc;
        if (flags & 8) {
            const bool hi = (bcol >= BN);
            Bph = hi ? B2h : Bmh;  Bpl = hi ? B2l : Bml;  bc = 0;
        } else {
            Bph = s ? B2h : Bmh;   Bpl = s ? B2l : Bml;   bc = bcol;
        }
        const int afc = (tid & 3) * 4;
        rA[0] = *(const float4*)(Ap + (size_t)(brow + arow0) * K + k0 + afc);
        rA[1] = *(const float4*)(Ap + (size_t)(brow + arow0 + 64) * K + k0 + afc);
        const size_t boff = (size_t)(k0 / 2 + brw) * ldb + bc + bfc;
        rBh = *(const uint4*)(Bph + boff);
        rBl = *(const uint4*)(Bpl + boff);
    };

    auto storeTile = [&](int buf) {
#pragma unroll
        for (int p = 0; p < 2; p++) {
            const float4 v = rA[p];
            const float h0 = bf16hi(v.x), h1 = bf16hi(v.y);
            const float h2 = bf16hi(v.z), h3 = bf16hi(v.w);
            const int base = (arow0 + p * 64) * AST + (tid & 3) * 2;
            *(uint2*)&As[buf][0][base] = make_uint2(pack_bf16(h0, h1), pack_bf16(h2, h3));
            *(uint2*)&As[buf][1][base] = make_uint2(pack_bf16(v.x - h0, v.y - h1),
                                                    pack_bf16(v.z - h2, v.w - h3));
        }
        const int base = brw * BST + bfc;
        *(uint4*)&Bs[buf][0][base] = rBh;
        *(uint4*)&Bs[buf][1][base] = rBl;
    };

    loadTile(0);
    storeTile(0);
    __syncthreads();

    for (int t = 0; t < ntiles; t++) {
        if (t + 1 < ntiles) loadTile(t + 1);

        const int cur = t & 1;
        const unsigned* Bsh = Bs[cur][0];
        const unsigned* Bsl = Bs[cur][1];
        const unsigned aTileH = aSmemBase + (unsigned)(cur * (2 * BM * AST * 4)) + laneOff;
        const unsigned aTileL = aTileH + (unsigned)(BM * AST * 4);

        unsigned bh[4][2], bl[4][2];
#pragma unroll
        for (int ns = 0; ns < 4; ns++) {
            const int n = wn + ns * 8 + gid;
            bh[ns][0] = Bsh[tig * BST + n];
            bh[ns][1] = Bsh[(tig + 4) * BST + n];
            bl[ns][0] = Bsl[tig * BST + n];
            bl[ns][1] = Bsl[(tig + 4) * BST + n];
        }
#pragma unroll
        for (int ms = 0; ms < 4; ms++) {
            unsigned ah[4], al[4];
            ldsm_x4(ah[0], ah[1], ah[2], ah[3], aTileH + (unsigned)(ms * 16 * AST * 4));
            ldsm_x4(al[0], al[1], al[2], al[3], aTileL + (unsigned)(ms * 16 * AST * 4));
#pragma unroll
            for (int ns = 0; ns < 4; ns++) {
                mma_bf16(acc[ms][ns], ah, bh[ns]);
                mma_bf16(acc[ms][ns], ah, bl[ns]);
                mma_bf16(acc[ms][ns], al, bh[ns]);
            }
        }

        if (t + 1 < ntiles) {
            storeTile((t + 1) & 1);
            __syncthreads();
        }
    }

    // ---- fused value epilogue: atomicAdd(row, sum(relu(acc+bias)*vw)) ----
    if (flags & 16) {
#pragma unroll
        for (int ms = 0; ms < 4; ms++) {
            const int r0 = brow + wm + ms * 16 + gid;
            float p0 = 0.f, p1 = 0.f;
#pragma unroll
            for (int ns = 0; ns < 4; ns++) {
                const int c = bcol + wn + ns * 8 + tig * 2;
                const float b0 = bias[c], b1 = bias[c + 1];
                const float w0 = vw[c],  w1 = vw[c + 1];
                p0 += fmaxf(acc[ms][ns][0] + b0, 0.f) * w0
                    + fmaxf(acc[ms][ns][1] + b1, 0.f) * w1;
                p1 += fmaxf(acc[ms][ns][2] + b0, 0.f) * w0
                    + fmaxf(acc[ms][ns][3] + b1, 0.f) * w1;
            }
            p0 += __shfl_xor_sync(0xffffffffu, p0, 1);
            p0 += __shfl_xor_sync(0xffffffffu, p0, 2);
            p1 += __shfl_xor_sync(0xffffffffu, p1, 1);
            p1 += __shfl_xor_sync(0xffffffffu, p1, 2);
            if (tig == 0) {
                atomicAdd(&Cout[r0], p0);
                atomicAdd(&Cout[r0 + 8], p1);
            }
        }
        return;
    }

    const bool hasb   = (bias != nullptr);
    const bool resid  = (flags & 4);
    const bool dorelu = (flags & 5);
#pragma unroll
    for (int ms = 0; ms < 4; ms++) {
        const int r0 = brow + wm + ms * 16 + gid;
        const int r1 = r0 + 8;
        float alive0 = 1.f, alive1 = 1.f;
        const float *E0 = nullptr, *E1 = nullptr;
        if (resid) {
            alive0 = dones[r0] ? 0.f : 1.f;
            alive1 = dones[r1] ? 0.f : 1.f;
            E0 = Ein + (size_t)r0 * N;
            E1 = Ein + (size_t)r1 * N;
        }
#pragma unroll
        for (int ns = 0; ns < 4; ns++) {
            const int c = bcol + wn + ns * 8 + tig * 2;
            float b0 = 0.f, b1 = 0.f;
            if (hasb) { b0 = bias[c]; b1 = bias[c + 1]; }
            float v0 = acc[ms][ns][0] + b0;
            float v1 = acc[ms][ns][1] + b1;
            float v2 = acc[ms][ns][2] + b0;
            float v3 = acc[ms][ns][3] + b1;
            if (dorelu) {
                v0 = fmaxf(v0, 0.f); v1 = fmaxf(v1, 0.f);
                v2 = fmaxf(v2, 0.f); v3 = fmaxf(v3, 0.f);
            }
            if (resid) {
                v0 = (E0[c] + v0) * alive0;     v1 = (E0[c + 1] + v1) * alive0;
                v2 = (E1[c] + v2) * alive1;     v3 = (E1[c + 1] + v3) * alive1;
            }
            *(float2*)&Cout[(size_t)r0 * N + c] = make_float2(v0, v1);
            *(float2*)&Cout[(size_t)r1 * N + c] = make_float2(v2, v3);
        }
    }
}

// ---------------- persistent GRU scan v3: k-split, 768 threads -----------------
// thread = (column, k-half): w[32] regs; gates phase = 1 item/thread.
#define RPB 4
#define GTH 768

__device__ __forceinline__ unsigned long long fma_f32x2(
    unsigned long long a, unsigned long long b, unsigned long long c)
{
    unsigned long long d;
    asm("fma.rn.f32x2 %0, %1, %2, %3;" : "=l"(d) : "l"(a), "l"(b), "l"(c));
    return d;
}

__device__ __forceinline__ float sig_fast(float x)
{
    return __fdividef(1.f, 1.f + __expf(-x));
}
__device__ __forceinline__ float tanh_fast(float x)
{
    return __fdividef(2.f, 1.f + __expf(-2.f * x)) - 1.f;
}

__global__ __launch_bounds__(GTH, 1) void gru_kernel(
    const float* __restrict__ gi,
    const unsigned char* __restrict__ dones,
    const float* __restrict__ h0,
    const float* __restrict__ Wh,
    const float* __restrict__ bhn,
    float* __restrict__ e_out,
    float* __restrict__ hidden_out)
{
    __shared__ __align__(16) float hs2[64 * 8];     // [kpair][r*2 + (lo/hi)]
    __shared__ float ghsP[2 * RPB * 384];           // [kh][r][col]
    __shared__ float sbhn[D];
    __shared__ unsigned char sdn[T_STEPS * RPB];

    const int tid = threadIdx.x;
    const int rowbase = blockIdx.x * RPB;
    const int col = (tid >= 384) ? tid - 384 : tid;   // 0..383
    const int kh  = (tid >= 384) ? 1 : 0;             // k-half

    // Wh column slice -> 32 f32x2 registers
    unsigned long long w[32];
#pragma unroll
    for (int kp = 0; kp < 32; kp++) {
        const int k0 = kh * 64 + 2 * kp;
        const unsigned lo = __float_as_uint(Wh[(size_t)k0 * 384 + col]);
        const unsigned hi = __float_as_uint(Wh[(size_t)(k0 + 1) * 384 + col]);
        w[kp] = ((unsigned long long)hi << 32) | lo;
    }
    if (tid < D) sbhn[tid] = bhn[tid];
    if (tid < T_STEPS)
        *(uchar4*)&sdn[tid * 4] = *(const uchar4*)&dones[tid * BATCH + rowbase];

    // gates mapping: 1 item per thread for tid < 512
    const bool gact = (tid < 512);
    const int gr = tid >> 7, gd = tid & 127;
    const int grow = rowbase + gr;

    float pa0 = 0.f, pa1 = 0.f, pa2 = 0.f;
    auto prefetch = [&](int t) {
        if (gact) {
            const size_t gib = ((size_t)t * BATCH + grow) * (3 * D);
            pa0 = gi[gib + gd];
            pa1 = gi[gib + D + gd];
            pa2 = gi[gib + 2 * D + gd];
        }
    };

    prefetch(0);
    __syncthreads();   // sdn visible

    if (gact) {
        const float v = sdn[gr] ? 0.f : h0[(size_t)grow * D + gd];
        hs2[(gd >> 1) * 8 + gr * 2 + (gd & 1)] = v;
    }
    __syncthreads();

    const int khBase = kh * 32;
    float* ghMine = ghsP + kh * (RPB * 384);

    for (int t = 0; t < T_STEPS; t++) {
        // partial gemv over this thread's k-half
        {
            unsigned long long a0 = 0, a1 = 0, a2 = 0, a3 = 0;
#pragma unroll
            for (int kp = 0; kp < 32; kp++) {
                const float* hp = hs2 + (khBase + kp) * 8;
                const ulonglong2 p01 = *(const ulonglong2*)hp;
                const ulonglong2 p23 = *(const ulonglong2*)(hp + 4);
                a0 = fma_f32x2(w[kp], p01.x, a0);
                a1 = fma_f32x2(w[kp], p01.y, a1);
                a2 = fma_f32x2(w[kp], p23.x, a2);
                a3 = fma_f32x2(w[kp], p23.y, a3);
            }
            ghMine[0 * 384 + col] = __uint_as_float((unsigned)a0) + __uint_as_float((unsigned)(a0 >> 32));
            ghMine[1 * 384 + col] = __uint_as_float((unsigned)a1) + __uint_as_float((unsigned)(a1 >> 32));
            ghMine[2 * 384 + col] = __uint_as_float((unsigned)a2) + __uint_as_float((unsigned)(a2 >> 32));
            ghMine[3 * 384 + col] = __uint_as_float((unsigned)a3) + __uint_as_float((unsigned)(a3 >> 32));
        }
        __syncthreads();

        if (gact) {
            const float* g0 = ghsP + gr * 384;
            const float* g1 = ghsP + RPB * 384 + gr * 384;
            const float h_r = g0[gd]           + g1[gd];
            const float h_z = g0[D + gd]       + g1[D + gd];
            const float h_n = g0[2 * D + gd]   + g1[2 * D + gd];
            const int hsidx = (gd >> 1) * 8 + gr * 2 + (gd & 1);
            const float hprev = hs2[hsidx];
            const float rg = sig_fast(pa0 + h_r);
            const float zg = sig_fast(pa1 + h_z);
            const float ng = tanh_fast(pa2 + rg * (h_n + sbhn[gd]));
            const float hn = (1.f - zg) * ng + zg * hprev;
            const float alive = sdn[t * 4 + gr] ? 0.f : 1.f;
            e_out[((size_t)t * BATCH + grow) * D + gd] = hn * alive;
            if (t == T_STEPS - 1) hidden_out[(size_t)grow * D + gd] = hn;
            else hs2[hsidx] = sdn[(t + 1) * 4 + gr] ? 0.f : hn;
        }
        if (t + 1 < T_STEPS) prefetch(t + 1);
        __syncthreads();
    }
}

// ---------------- fused pairwise-coupling C + context (lane-parallel j) --------
__global__ __launch_bounds__(256) void couple_ctx_kernel(
    const float* __restrict__ e, const float* __restrict__ aiaj,
    const float* __restrict__ chb,
    const float* __restrict__ cow, const float* __restrict__ cob,
    float* __restrict__ ctx)
{
    __shared__ float sai[NA * 132];
    __shared__ float sajt[128 * 9];
    __shared__ float se[NA * D];
    __shared__ float sb[CH], sw[CH];
    __shared__ float sC[NA * NA];

    const int g  = blockIdx.x;
    const size_t base  = (size_t)g * NA * D;
    const size_t base2 = (size_t)g * NA * 256;
    const int tid = threadIdx.x;
    const int lane = tid & 31, warp = tid >> 5;

    {
        const int j = warp;
        const int k0 = lane * 4;
        const float4 vi = *(const float4*)&aiaj[base2 + j * 256 + k0];
        const float4 vj = *(const float4*)&aiaj[base2 + j * 256 + 128 + k0];
        *(float4*)&sai[j * 132 + k0] = vi;
        sajt[(k0 + 0) * 9 + j] = vj.x;
        sajt[(k0 + 1) * 9 + j] = vj.y;
        sajt[(k0 + 2) * 9 + j] = vj.z;
        sajt[(k0 + 3) * 9 + j] = vj.w;
    }
    *(float4*)&se[tid * 4] = *(const float4*)&e[base + tid * 4];
    if (tid < CH) { sb[tid] = chb[tid]; sw[tid] = cow[tid]; }
    __syncthreads();

    {
        const int i = warp;
        const int jj = lane & 7, slice = lane >> 3;
        const float cb = cob[0];
        float s = 0.f;
#pragma unroll
        for (int it = 0; it < 32; it++) {
            const int kk = slice * 32 + ((it + slice * 8) & 31);
            const float v = sai[i * 132 + kk] + sajt[kk * 9 + jj] + sb[kk];
            s += fmaxf(v, 0.f) * sw[kk];
        }
        s += __shfl_xor_sync(0xffffffffu, s, 8);
        s += __shfl_xor_sync(0xffffffffu, s, 16);
        if (lane < 8)
            sC[i * NA + lane] = (i == lane) ? 0.f : 1.f / (1.f + expf(-(s + cb)));
    }
    __syncthreads();

    for (int idx = tid; idx < NA * D; idx += 256) {
        const int i = idx >> 7, d = idx & 127;
        float s = 0.f;
#pragma unroll
        for (int j = 0; j < NA; j++) s += sC[i * NA + j] * se[j * D + d];
        ctx[base + idx] = s;
    }
}

// ---------------- launcher -------------------------------------------------------
extern "C" void kernel_launch(void* const* d_in, const int* in_sizes, int n_in,
                              void* d_out, int out_size)
{
    const float* hidden = (const float*)d_in[0];
    const float* obs    = (const float*)d_in[1];
    const void*  dones_raw = d_in[2];
    const float* e1w = (const float*)d_in[3];
    const float* e1b = (const float*)d_in[4];
    const float* e2w = (const float*)d_in[5];
    const float* e2b = (const float*)d_in[6];
    const float* gWi = (const float*)d_in[7];
    const float* gbi = (const float*)d_in[8];
    const float* gWh = (const float*)d_in[9];
    const float* gbhn = (const float*)d_in[10];
    const float* chw = (const float*)d_in[11];
    const float* chb = (const float*)d_in[12];
    const float* cow = (const float*)d_in[13];
    const float* cob = (const float*)d_in[14];
    const float* uhw = (const float*)d_in[15];
    const float* uhb = (const float*)d_in[16];
    const float* uow = (const float*)d_in[17];
    const float* uob = (const float*)d_in[18];
    const float* v1w = (const float*)d_in[19];
    const float* v1b = (const float*)d_in[20];
    const float* v2w = (const float*)d_in[21];
    const float* v2b = (const float*)d_in[22];
    const float* vow = (const float*)d_in[23];
    const float* vob = (const float*)d_in[24];

    float* out_hidden = (float*)d_out;                 // (B, D)
    float* out_values = (float*)d_out + BATCH * D;     // (T, B)

    float *emb1, *emb2, *gi, *e, *aiaj, *ctx, *d1, *v1;
    unsigned char* dmask;
    unsigned* wpk;
    cudaGetSymbolAddress((void**)&emb1, g_emb1);
    cudaGetSymbolAddress((void**)&emb2, g_emb2);
    cudaGetSymbolAddress((void**)&gi,   g_gi);
    cudaGetSymbolAddress((void**)&e,    g_e);
    cudaGetSymbolAddress((void**)&aiaj, g_aiaj);
    cudaGetSymbolAddress((void**)&ctx,  g_ctx);
    cudaGetSymbolAddress((void**)&d1,   g_d1);
    cudaGetSymbolAddress((void**)&v1,   g_v1);
    cudaGetSymbolAddress((void**)&dmask, g_dmask);
    cudaGetSymbolAddress((void**)&wpk,  g_wpk);

    unsigned* e1wP = wpk + 0;        // sz 4096
    unsigned* e2wP = wpk + 8192;     // sz 8192
    unsigned* gWiP = wpk + 24576;    // sz 24576
    unsigned* chwP = wpk + 73728;    // sz 16384
    unsigned* uhwP = wpk + 106496;   // sz 16384
    unsigned* uowP = wpk + 139264;   // sz 8192
    unsigned* v1wP = wpk + 155648;   // sz 16384
    unsigned* v2wP = wpk + 188416;   // sz 32768

    const int M = TB;
    const dim3 blk(256);

    detect_dones_kernel<<<1, 256>>>((const unsigned char*)dones_raw, TB);
    conv_dones_kernel<<<TB / 256, 256>>>(dones_raw, TB);
    pack_weights_kernel<<<(WPK_TOTAL + 255) / 256, 256>>>(
        e1w, e2w, gWi, chw, uhw, uow, v1w, v2w);

    // embed1: relu(obs @ e1w + e1b)
    tgemm_kernel<<<dim3(D / BN, M / BM), blk>>>(M, D, OBS, D, obs, nullptr,
        e1wP, e1wP + 4096, nullptr, nullptr, e1b, emb1, 1, nullptr, nullptr, nullptr);
    // embed2: relu(emb1 @ e2w + e2b)
    tgemm_kernel<<<dim3(D / BN, M / BM), blk>>>(M, D, D, D, emb1, nullptr,
        e2wP, e2wP + 8192, nullptr, nullptr, e2b, emb2, 1, nullptr, nullptr, nullptr);
    // gi = emb2 @ gWi + gbi
    tgemm_kernel<<<dim3(3 * D / BN, M / BM), blk>>>(M, 3 * D, D, 3 * D, emb2, nullptr,
        gWiP, gWiP + 24576, nullptr, nullptr, gbi, gi, 0, nullptr, nullptr, nullptr);
    // sequential GRU scan (k-split, 768 threads)
    gru_kernel<<<BATCH / RPB, GTH>>>(gi, dmask, hidden, gWh, gbhn, e, out_hidden);

    for (int it = 0; it < ITERS; it++) {
        // [ai | aj] = e @ [W1 | W2]
        tgemm_kernel<<<dim3(2 * CH / BN, M / BM), blk>>>(M, 2 * CH, D, CH, e, nullptr,
            chwP, chwP + 16384, chwP + 8192, chwP + 16384 + 8192,
            nullptr, aiaj, 8, nullptr, nullptr, nullptr);
        couple_ctx_kernel<<<T_STEPS * NE, 256>>>(e, aiaj, chb, cow, cob, ctx);
        // d1 = relu(e @ U1 + ctx @ U2 + uhb)
        tgemm_kernel<<<dim3(D / BN, M / BM), blk>>>(M, D, D, D, e, ctx,
            uhwP, uhwP + 16384, uhwP + 8192, uhwP + 16384 + 8192,
            uhb, d1, 1 | 2, nullptr, nullptr, nullptr);
        // e = (e + relu(d1 @ uow + uob)) * alive   (in place)
        tgemm_kernel<<<dim3(D / BN, M / BM), blk>>>(M, D, D, D, d1, nullptr,
            uowP, uowP + 8192, nullptr, nullptr, uob, e, 4, e, dmask, nullptr);
    }

    // value head: v1 = relu(e@v1w+b); values = relu(v1@v2w+v2b) . vow + vob (fused)
    tgemm_kernel<<<dim3(VH / BN, M / BM), blk>>>(M, VH, D, VH, e, nullptr,
        v1wP, v1wP + 16384, nullptr, nullptr, v1b, v1, 1, nullptr, nullptr, nullptr);
    init_values_kernel<<<TB / 256, 256>>>(out_values, vob);
    tgemm_kernel<<<dim3(VH / BN, M / BM), blk>>>(M, VH, VH, VH, v1, nullptr,
        v2wP, v2wP + 32768, nullptr, nullptr, v2b, out_values, 1 | 16,
        nullptr, nullptr, vow);
}

// round 16
// speedup vs baseline: 1.1312x; 1.1269x over previous
#include <cuda_runtime.h>
#include <cuda_bf16.h>
#include <math.h>

#define T_STEPS 128
#define NE 64
#define NA 8
#define OBS 64
#define D 128
#define CH 128
#define VH 256
#define BATCH 512           // NE*NA
#define TB (T_STEPS*BATCH)  // 65536
#define ITERS 2

// ---------------- scratch (static device arrays: allocation-free) -------------
__device__ float g_emb1[TB * D];
__device__ float g_emb2[TB * D];
__device__ float g_gi[TB * 3 * D];
__device__ float g_e[TB * D];
__device__ float g_aiaj[TB * 2 * CH];
__device__ float g_ctx[TB * D];
__device__ float g_d1[TB * D];
__device__ float g_v1[TB * VH];
__device__ unsigned char g_dmask[TB];
__device__ int g_dflag;
__device__ unsigned g_wpk[253952];      // packed bf16 hi/lo weights (u32)
__device__ unsigned g_whb[2 * 48 * 512]; // GRU Wh as per-thread B fragments (hi|lo)
#define WPK_TOTAL 126976

// ---------------- dones dtype detection + canonicalization --------------------
__global__ void detect_dones_kernel(const unsigned char* __restrict__ p, int n)
{
    __shared__ int s_nonbin, s_off4;
    if (threadIdx.x == 0) { s_nonbin = 0; s_off4 = 0; }
    __syncthreads();
    int nb = 0, o4 = 0;
    for (int i = threadIdx.x; i < n; i += blockDim.x) {
        const unsigned char b = p[i];
        if (b > 1) nb = 1;
        else if (b == 1 && (i & 3)) o4 = 1;
    }
    if (nb) atomicOr(&s_nonbin, 1);
    if (o4) atomicOr(&s_off4, 1);
    __syncthreads();
    if (threadIdx.x == 0)
        g_dflag = s_nonbin ? 1 : (s_off4 ? 0 : 2);
}

__global__ void conv_dones_kernel(const void* __restrict__ p, int n)
{
    const int i = blockIdx.x * blockDim.x + threadIdx.x;
    if (i >= n) return;
    const int f = g_dflag;
    unsigned char m;
    if (f == 1)      m = (((const float*)p)[i] != 0.f);
    else if (f == 2) m = (((const int*)p)[i] != 0);
    else             m = (((const unsigned char*)p)[i] != 0);
    g_dmask[i] = m;
}

// ---------------- bf16 helpers -------------------------------------------------
__device__ __forceinline__ unsigned pack_bf16(float lo_elem, float hi_elem)
{
    unsigned d;
    asm("cvt.rn.bf16x2.f32 %0, %1, %2;" : "=r"(d) : "f"(hi_elem), "f"(lo_elem));
    return d;
}

__device__ __forceinline__ float bf16hi(float x)
{
    return __bfloat162float(__float2bfloat16(x));
}

// ---------------- one-time weight packing --------------------------------------
__global__ void pack_weights_kernel(
    const float* __restrict__ s0, const float* __restrict__ s1,
    const float* __restrict__ s2, const float* __restrict__ s3,
    const float* __restrict__ s4, const float* __restrict__ s5,
    const float* __restrict__ s6, const float* __restrict__ s7)
{
    const int idx = blockIdx.x * blockDim.x + threadIdx.x;
    if (idx >= WPK_TOTAL) return;
    const int cum[9]  = {0, 4096, 12288, 36864, 53248, 69632, 77824, 94208, 126976};
    const int hoff[8] = {0, 8192, 24576, 73728, 106496, 139264, 155648, 188416};
    const int Ns[8]   = {128, 128, 384, 128, 128, 128, 256, 256};
    int m = 0;
#pragma unroll
    for (int q = 0; q < 7; q++) if (idx >= cum[q + 1]) m = q + 1;
    const float* srcs[8] = {s0, s1, s2, s3, s4, s5, s6, s7};
    const int local = idx - cum[m];
    const int N = Ns[m];
    const int kp = local / N;
    const int n  = local - kp * N;
    const float* S = srcs[m];
    const float v0 = S[(size_t)(2 * kp) * N + n];
    const float v1 = S[(size_t)(2 * kp + 1) * N + n];
    const float h0 = bf16hi(v0), h1 = bf16hi(v1);
    const int sz = cum[m + 1] - cum[m];
    g_wpk[hoff[m] + local]      = pack_bf16(h0, h1);
    g_wpk[hoff[m] + sz + local] = pack_bf16(v0 - h0, v1 - h1);
}

// GRU Wh -> per-thread mma B fragments.
// thread t = w*32+lane; frag index i = kt*6 + nt*2 + reg (48 per thread).
// n = w*24 + nt*8 + gid ; k0 = kt*16 + reg*8 + 2*tig.
__global__ void pack_whb_kernel(const float* __restrict__ Wh)
{
    const int idx = blockIdx.x * blockDim.x + threadIdx.x;
    if (idx >= 48 * 512) return;
    const int i = idx >> 9, t = idx & 511;
    const int kt = i / 6, rem = i % 6, nt = rem >> 1, reg = rem & 1;
    const int w = t >> 5, lane = t & 31, gid = lane >> 2, tig = lane & 3;
    const int n  = w * 24 + nt * 8 + gid;
    const int k0 = kt * 16 + reg * 8 + 2 * tig;
    const float v0 = Wh[(size_t)k0 * 384 + n];
    const float v1 = Wh[(size_t)(k0 + 1) * 384 + n];
    const float h0 = bf16hi(v0), h1 = bf16hi(v1);
    g_whb[idx]            = pack_bf16(h0, h1);
    g_whb[48 * 512 + idx] = pack_bf16(v0 - h0, v1 - h1);
}

// ---------------- init values buffer -------------------------------------------
__global__ void init_values_kernel(float* __restrict__ out, const float* __restrict__ b)
{
    out[blockIdx.x * blockDim.x + threadIdx.x] = b[0];
}

// ---------------- BF16 tensor-core GEMM (pre-packed weights) -------------------
// flags: 1 relu | 2 dual-source | 4 resid+alive | 8 B column-split | 16 fused vout
#define BM 128
#define BN 128
#define BK 16
#define AST 12
#define BST 136

__device__ __forceinline__ void mma_bf16(float* c, const unsigned* a, const unsigned* b)
{
    asm volatile(
        "mma.sync.aligned.m16n8k16.row.col.f32.bf16.bf16.f32 "
        "{%0,%1,%2,%3}, {%4,%5,%6,%7}, {%8,%9}, {%0,%1,%2,%3};"
        : "+f"(c[0]), "+f"(c[1]), "+f"(c[2]), "+f"(c[3])
        : "r"(a[0]), "r"(a[1]), "r"(a[2]), "r"(a[3]), "r"(b[0]), "r"(b[1]));
}

__device__ __forceinline__ void ldsm_x4(unsigned& r0, unsigned& r1, unsigned& r2,
                                        unsigned& r3, unsigned addr)
{
    asm volatile("ldmatrix.sync.aligned.m8n8.x4.shared.b16 {%0,%1,%2,%3}, [%4];"
                 : "=r"(r0), "=r"(r1), "=r"(r2), "=r"(r3) : "r"(addr));
}

__global__ __launch_bounds__(256) void tgemm_kernel(
    int M, int N, int K, int ldb,
    const float* __restrict__ A, const float* __restrict__ A2,
    const unsigned* __restrict__ Bmh, const unsigned* __restrict__ Bml,
    const unsigned* __restrict__ B2h, const unsigned* __restrict__ B2l,
    const float* __restrict__ bias, float* __restrict__ Cout,
    int flags, const float* __restrict__ Ein,
    const unsigned char* __restrict__ dones,
    const float* __restrict__ vw)
{
    __shared__ __align__(16) unsigned As[2][2][BM * AST];
    __shared__ __align__(16) unsigned Bs[2][2][(BK / 2) * BST];

    const int tid  = threadIdx.x;
    const int brow = blockIdx.y * BM;
    const int bcol = blockIdx.x * BN;
    const int w    = tid >> 5, lane = tid & 31;
    const int gid  = lane >> 2, tig = lane & 3;
    const int wm   = (w & 1) * 64;
    const int wn   = (w >> 1) * 32;

    const int arow0 = tid >> 2;
    const int brw   = tid >> 5;
    const int bfc   = (tid & 31) * 4;

    const unsigned aSmemBase = (unsigned)__cvta_generic_to_shared(&As[0][0][0]);
    const unsigned laneOff = ((wm + (lane & 15)) * AST + ((lane & 16) >> 2)) * 4;

    float acc[4][4][4];
#pragma unroll
    for (int i = 0; i < 4; i++)
#pragma unroll
        for (int j = 0; j < 4; j++)
#pragma unroll
            for (int q = 0; q < 4; q++) acc[i][j][q] = 0.f;

    const int nsrc = (flags & 2) ? 2 : 1;
    const int tilesPerSrc = K / BK;
    const int ntiles = nsrc * tilesPerSrc;

    float4 rA[2];
    uint4 rBh, rBl;

    auto loadTile = [&](int t) {
        const int s  = (t >= tilesPerSrc) ? 1 : 0;
        const int k0 = (t - s * tilesPerSrc) * BK;
        const float* Ap = s ? A2 : A;
        const unsigned *Bph, *Bpl;
        int bc;
        if (flags & 8) {
            const bool hi = (bcol >= BN);
            Bph = hi ? B2h : Bmh;  Bpl = hi ? B2l : Bml;  bc = 0;
        } else {
            Bph = s ? B2h : Bmh;   Bpl = s ? B2l : Bml;   bc = bcol;
        }
        const int afc = (tid & 3) * 4;
        rA[0] = *(const float4*)(Ap + (size_t)(brow + arow0) * K + k0 + afc);
        rA[1] = *(const float4*)(Ap + (size_t)(brow + arow0 + 64) * K + k0 + afc);
        const size_t boff = (size_t)(k0 / 2 + brw) * ldb + bc + bfc;
        rBh = *(const uint4*)(Bph + boff);
        rBl = *(const uint4*)(Bpl + boff);
    };

    auto storeTile = [&](int buf) {
#pragma unroll
        for (int p = 0; p < 2; p++) {
            const float4 v = rA[p];
            const float h0 = bf16hi(v.x), h1 = bf16hi(v.y);
            const float h2 = bf16hi(v.z), h3 = bf16hi(v.w);
            const int base = (arow0 + p * 64) * AST + (tid & 3) * 2;
            *(uint2*)&As[buf][0][base] = make_uint2(pack_bf16(h0, h1), pack_bf16(h2, h3));
            *(uint2*)&As[buf][1][base] = make_uint2(pack_bf16(v.x - h0, v.y - h1),
                                                    pack_bf16(v.z - h2, v.w - h3));
        }
        const int base = brw * BST + bfc;
        *(uint4*)&Bs[buf][0][base] = rBh;
        *(uint4*)&Bs[buf][1][base] = rBl;
    };

    loadTile(0);
    storeTile(0);
    __syncthreads();

    for (int t = 0; t < ntiles; t++) {
        if (t + 1 < ntiles) loadTile(t + 1);

        const int cur = t & 1;
        const unsigned* Bsh = Bs[cur][0];
        const unsigned* Bsl = Bs[cur][1];
        const unsigned aTileH = aSmemBase + (unsigned)(cur * (2 * BM * AST * 4)) + laneOff;
        const unsigned aTileL = aTileH + (unsigned)(BM * AST * 4);

        unsigned bh[4][2], bl[4][2];
#pragma unroll
        for (int ns = 0; ns < 4; ns++) {
            const int n = wn + ns * 8 + gid;
            bh[ns][0] = Bsh[tig * BST + n];
            bh[ns][1] = Bsh[(tig + 4) * BST + n];
            bl[ns][0] = Bsl[tig * BST + n];
            bl[ns][1] = Bsl[(tig + 4) * BST + n];
        }
#pragma unroll
        for (int ms = 0; ms < 4; ms++) {
            unsigned ah[4], al[4];
            ldsm_x4(ah[0], ah[1], ah[2], ah[3], aTileH + (unsigned)(ms * 16 * AST * 4));
            ldsm_x4(al[0], al[1], al[2], al[3], aTileL + (unsigned)(ms * 16 * AST * 4));
#pragma unroll
            for (int ns = 0; ns < 4; ns++) {
                mma_bf16(acc[ms][ns], ah, bh[ns]);
                mma_bf16(acc[ms][ns], ah, bl[ns]);
                mma_bf16(acc[ms][ns], al, bh[ns]);
            }
        }

        if (t + 1 < ntiles) {
            storeTile((t + 1) & 1);
            __syncthreads();
        }
    }

    // ---- fused value epilogue ----
    if (flags & 16) {
#pragma unroll
        for (int ms = 0; ms < 4; ms++) {
            const int r0 = brow + wm + ms * 16 + gid;
            float p0 = 0.f, p1 = 0.f;
#pragma unroll
            for (int ns = 0; ns < 4; ns++) {
                const int c = bcol + wn + ns * 8 + tig * 2;
                const float b0 = bias[c], b1 = bias[c + 1];
                const float w0 = vw[c],  w1 = vw[c + 1];
                p0 += fmaxf(acc[ms][ns][0] + b0, 0.f) * w0
                    + fmaxf(acc[ms][ns][1] + b1, 0.f) * w1;
                p1 += fmaxf(acc[ms][ns][2] + b0, 0.f) * w0
                    + fmaxf(acc[ms][ns][3] + b1, 0.f) * w1;
            }
            p0 += __shfl_xor_sync(0xffffffffu, p0, 1);
            p0 += __shfl_xor_sync(0xffffffffu, p0, 2);
            p1 += __shfl_xor_sync(0xffffffffu, p1, 1);
            p1 += __shfl_xor_sync(0xffffffffu, p1, 2);
            if (tig == 0) {
                atomicAdd(&Cout[r0], p0);
                atomicAdd(&Cout[r0 + 8], p1);
            }
        }
        return;
    }

    const bool hasb   = (bias != nullptr);
    const bool resid  = (flags & 4);
    const bool dorelu = (flags & 5);
#pragma unroll
    for (int ms = 0; ms < 4; ms++) {
        const int r0 = brow + wm + ms * 16 + gid;
        const int r1 = r0 + 8;
        float alive0 = 1.f, alive1 = 1.f;
        const float *E0 = nullptr, *E1 = nullptr;
        if (resid) {
            alive0 = dones[r0] ? 0.f : 1.f;
            alive1 = dones[r1] ? 0.f : 1.f;
            E0 = Ein + (size_t)r0 * N;
            E1 = Ein + (size_t)r1 * N;
        }
#pragma unroll
        for (int ns = 0; ns < 4; ns++) {
            const int c = bcol + wn + ns * 8 + tig * 2;
            float b0 = 0.f, b1 = 0.f;
            if (hasb) { b0 = bias[c]; b1 = bias[c + 1]; }
            float v0 = acc[ms][ns][0] + b0;
            float v1 = acc[ms][ns][1] + b1;
            float v2 = acc[ms][ns][2] + b0;
            float v3 = acc[ms][ns][3] + b1;
            if (dorelu) {
                v0 = fmaxf(v0, 0.f); v1 = fmaxf(v1, 0.f);
                v2 = fmaxf(v2, 0.f); v3 = fmaxf(v3, 0.f);
            }
            if (resid) {
                v0 = (E0[c] + v0) * alive0;     v1 = (E0[c + 1] + v1) * alive0;
                v2 = (E1[c] + v2) * alive1;     v3 = (E1[c + 1] + v3) * alive1;
            }
            *(float2*)&Cout[(size_t)r0 * N + c] = make_float2(v0, v1);
            *(float2*)&Cout[(size_t)r1 * N + c] = make_float2(v2, v3);
        }
    }
}

// ---------------- GRU scan v4: tensor-core gemv, Wh in register B-frags --------
// 128 blocks x 4 rows; 512 threads = 16 warps, each warp owns 24 gh columns.
// h lives in smem as an mma A-tile (16 rows: 4 real + 12 zero-pad), bf16 hi/lo.
#define RPB 4
#define GTH 512

__device__ __forceinline__ float sig_fast(float x)
{
    return __fdividef(1.f, 1.f + __expf(-x));
}
__device__ __forceinline__ float tanh_fast(float x)
{
    return __fdividef(2.f, 1.f + __expf(-2.f * x)) - 1.f;
}

__global__ __launch_bounds__(GTH, 1) void gru_kernel(
    const float* __restrict__ gi,            // (T,B,3D)
    const unsigned char* __restrict__ dones, // (T,B)
    const float* __restrict__ h0,            // (B,D)
    const unsigned* __restrict__ whb,        // packed Wh B-fragments
    const float* __restrict__ bhn,
    float* __restrict__ e_out,               // (T,B,D)
    float* __restrict__ hidden_out)          // (B,D)
{
    __shared__ __align__(16) unsigned sA[2 * 16 * 68];   // A-tile hi | lo (stride 68)
    __shared__ float hs[RPB * 132];                       // fp32 h
    __shared__ float ghs[RPB * 388];                      // gh per row
    __shared__ float sbhn[D];
    __shared__ unsigned char sdn[T_STEPS * RPB];

    const int tid = threadIdx.x;
    const int rowbase = blockIdx.x * RPB;
    const int w = tid >> 5, lane = tid & 31;
    const int gid = lane >> 2, tig = lane & 3;

    // Wh B fragments -> registers (coalesced: [frag][tid])
    unsigned bh[48], bl[48];
#pragma unroll
    for (int i = 0; i < 48; i++) {
        bh[i] = whb[i * 512 + tid];
        bl[i] = whb[48 * 512 + i * 512 + tid];
    }

    if (tid < D) sbhn[tid] = bhn[tid];
    if (tid < T_STEPS)
        *(uchar4*)&sdn[tid * 4] = *(const uchar4*)&dones[tid * BATCH + rowbase];
    // zero pad rows 4..15 of A-tile (hi + lo)
    for (int i = tid; i < 12 * 68; i += GTH) {
        const int rr = 4 + i / 68, cc = i % 68;
        sA[rr * 68 + cc] = 0u;
        sA[16 * 68 + rr * 68 + cc] = 0u;
    }

    const int r = tid >> 7, d = tid & 127;
    const int row = rowbase + r;

    float pa0, pa1, pa2;
    auto prefetch = [&](int t) {
        const size_t gib = ((size_t)t * BATCH + row) * (3 * D);
        pa0 = gi[gib + d];
        pa1 = gi[gib + D + d];
        pa2 = gi[gib + 2 * D + d];
    };
    prefetch(0);
    __syncthreads();   // sdn + pad visible

    // init h (dones[0] reset): fp32 + A-tile bf16 hi/lo
    {
        const float v = sdn[r] ? 0.f : h0[(size_t)row * D + d];
        hs[r * 132 + d] = v;
        const float vo = __shfl_down_sync(0xffffffffu, v, 1);
        if (!(d & 1)) {
            const float h0p = bf16hi(v), h1p = bf16hi(vo);
            sA[r * 68 + (d >> 1)] = pack_bf16(h0p, h1p);
            sA[16 * 68 + r * 68 + (d >> 1)] = pack_bf16(v - h0p, vo - h1p);
        }
    }
    __syncthreads();

    const unsigned smA = (unsigned)__cvta_generic_to_shared(sA);
    const unsigned aOffBase = smA + ((lane & 15) * 68 + ((lane & 16) >> 2)) * 4;

    for (int t = 0; t < T_STEPS; t++) {
        // gemv via mma: gh[0:4][384] = h(4x128) @ Wh(128x384), bf16 3-product
        float acc[3][4];
#pragma unroll
        for (int nt = 0; nt < 3; nt++)
#pragma unroll
            for (int q = 0; q < 4; q++) acc[nt][q] = 0.f;

#pragma unroll
        for (int kt = 0; kt < 8; kt++) {
            unsigned ah[4], al[4];
            ldsm_x4(ah[0], ah[1], ah[2], ah[3], aOffBase + (unsigned)(kt * 8 * 4));
            ldsm_x4(al[0], al[1], al[2], al[3], aOffBase + (unsigned)((16 * 68 + kt * 8) * 4));
#pragma unroll
            for (int nt = 0; nt < 3; nt++) {
                mma_bf16(acc[nt], ah, &bh[kt * 6 + nt * 2]);
                mma_bf16(acc[nt], ah, &bl[kt * 6 + nt * 2]);
                mma_bf16(acc[nt], al, &bh[kt * 6 + nt * 2]);
            }
        }
        if (gid < 4) {   // rows 0-3 valid (4-15 are zero padding)
#pragma unroll
            for (int nt = 0; nt < 3; nt++) {
                const int n = w * 24 + nt * 8 + tig * 2;
                *(float2*)&ghs[gid * 388 + n] = make_float2(acc[nt][0], acc[nt][1]);
            }
        }
        __syncthreads();

        // gates: 1 item per thread
        {
            const float h_r = ghs[r * 388 + d];
            const float h_z = ghs[r * 388 + 128 + d];
            const float h_n = ghs[r * 388 + 256 + d];
            const float hprev = hs[r * 132 + d];
            const float rg = sig_fast(pa0 + h_r);
            const float zg = sig_fast(pa1 + h_z);
            const float ng = tanh_fast(pa2 + rg * (h_n + sbhn[d]));
            const float hn = (1.f - zg) * ng + zg * hprev;
            const float alive = sdn[t * 4 + r] ? 0.f : 1.f;
            e_out[((size_t)t * BATCH + row) * D + d] = hn * alive;
            if (t == T_STEPS - 1) {
                hidden_out[(size_t)row * D + d] = hn;
            } else {
                const float hv = sdn[(t + 1) * 4 + r] ? 0.f : hn;
                hs[r * 132 + d] = hv;
                const float hvo = __shfl_down_sync(0xffffffffu, hv, 1);
                if (!(d & 1)) {
                    const float h0p = bf16hi(hv), h1p = bf16hi(hvo);
                    sA[r * 68 + (d >> 1)] = pack_bf16(h0p, h1p);
                    sA[16 * 68 + r * 68 + (d >> 1)] = pack_bf16(hv - h0p, hvo - h1p);
                }
            }
        }
        if (t + 1 < T_STEPS) prefetch(t + 1);
        __syncthreads();
    }
}

// ---------------- fused pairwise-coupling C + context (lane-parallel j) --------
__global__ __launch_bounds__(256) void couple_ctx_kernel(
    const float* __restrict__ e, const float* __restrict__ aiaj,
    const float* __restrict__ chb,
    const float* __restrict__ cow, const float* __restrict__ cob,
    float* __restrict__ ctx)
{
    __shared__ float sai[NA * 132];
    __shared__ float sajt[128 * 9];
    __shared__ float se[NA * D];
    __shared__ float sb[CH], sw[CH];
    __shared__ float sC[NA * NA];

    const int g  = blockIdx.x;
    const size_t base  = (size_t)g * NA * D;
    const size_t base2 = (size_t)g * NA * 256;
    const int tid = threadIdx.x;
    const int lane = tid & 31, warp = tid >> 5;

    {
        const int j = warp;
        const int k0 = lane * 4;
        const float4 vi = *(const float4*)&aiaj[base2 + j * 256 + k0];
        const float4 vj = *(const float4*)&aiaj[base2 + j * 256 + 128 + k0];
        *(float4*)&sai[j * 132 + k0] = vi;
        sajt[(k0 + 0) * 9 + j] = vj.x;
        sajt[(k0 + 1) * 9 + j] = vj.y;
        sajt[(k0 + 2) * 9 + j] = vj.z;
        sajt[(k0 + 3) * 9 + j] = vj.w;
    }
    *(float4*)&se[tid * 4] = *(const float4*)&e[base + tid * 4];
    if (tid < CH) { sb[tid] = chb[tid]; sw[tid] = cow[tid]; }
    __syncthreads();

    {
        const int i = warp;
        const int jj = lane & 7, slice = lane >> 3;
        const float cb = cob[0];
        float s = 0.f;
#pragma unroll
        for (int it = 0; it < 32; it++) {
            const int kk = slice * 32 + ((it + slice * 8) & 31);
            const float v = sai[i * 132 + kk] + sajt[kk * 9 + jj] + sb[kk];
            s += fmaxf(v, 0.f) * sw[kk];
        }
        s += __shfl_xor_sync(0xffffffffu, s, 8);
        s += __shfl_xor_sync(0xffffffffu, s, 16);
        if (lane < 8)
            sC[i * NA + lane] = (i == lane) ? 0.f : 1.f / (1.f + expf(-(s + cb)));
    }
    __syncthreads();

    for (int idx = tid; idx < NA * D; idx += 256) {
        const int i = idx >> 7, d = idx & 127;
        float s = 0.f;
#pragma unroll
        for (int j = 0; j < NA; j++) s += sC[i * NA + j] * se[j * D + d];
        ctx[base + idx] = s;
    }
}

// ---------------- launcher -------------------------------------------------------
extern "C" void kernel_launch(void* const* d_in, const int* in_sizes, int n_in,
                              void* d_out, int out_size)
{
    const float* hidden = (const float*)d_in[0];
    const float* obs    = (const float*)d_in[1];
    const void*  dones_raw = d_in[2];
    const float* e1w = (const float*)d_in[3];
    const float* e1b = (const float*)d_in[4];
    const float* e2w = (const float*)d_in[5];
    const float* e2b = (const float*)d_in[6];
    const float* gWi = (const float*)d_in[7];
    const float* gbi = (const float*)d_in[8];
    const float* gWh = (const float*)d_in[9];
    const float* gbhn = (const float*)d_in[10];
    const float* chw = (const float*)d_in[11];
    const float* chb = (const float*)d_in[12];
    const float* cow = (const float*)d_in[13];
    const float* cob = (const float*)d_in[14];
    const float* uhw = (const float*)d_in[15];
    const float* uhb = (const float*)d_in[16];
    const float* uow = (const float*)d_in[17];
    const float* uob = (const float*)d_in[18];
    const float* v1w = (const float*)d_in[19];
    const float* v1b = (const float*)d_in[20];
    const float* v2w = (const float*)d_in[21];
    const float* v2b = (const float*)d_in[22];
    const float* vow = (const float*)d_in[23];
    const float* vob = (const float*)d_in[24];

    float* out_hidden = (float*)d_out;                 // (B, D)
    float* out_values = (float*)d_out + BATCH * D;     // (T, B)

    float *emb1, *emb2, *gi, *e, *aiaj, *ctx, *d1, *v1;
    unsigned char* dmask;
    unsigned *wpk, *whb;
    cudaGetSymbolAddress((void**)&emb1, g_emb1);
    cudaGetSymbolAddress((void**)&emb2, g_emb2);
    cudaGetSymbolAddress((void**)&gi,   g_gi);
    cudaGetSymbolAddress((void**)&e,    g_e);
    cudaGetSymbolAddress((void**)&aiaj, g_aiaj);
    cudaGetSymbolAddress((void**)&ctx,  g_ctx);
    cudaGetSymbolAddress((void**)&d1,   g_d1);
    cudaGetSymbolAddress((void**)&v1,   g_v1);
    cudaGetSymbolAddress((void**)&dmask, g_dmask);
    cudaGetSymbolAddress((void**)&wpk,  g_wpk);
    cudaGetSymbolAddress((void**)&whb,  g_whb);

    unsigned* e1wP = wpk + 0;        // sz 4096
    unsigned* e2wP = wpk + 8192;     // sz 8192
    unsigned* gWiP = wpk + 24576;    // sz 24576
    unsigned* chwP = wpk + 73728;    // sz 16384
    unsigned* uhwP = wpk + 106496;   // sz 16384
    unsigned* uowP = wpk + 139264;   // sz 8192
    unsigned* v1wP = wpk + 155648;   // sz 16384
    unsigned* v2wP = wpk + 188416;   // sz 32768

    const int M = TB;
    const dim3 blk(256);

    detect_dones_kernel<<<1, 256>>>((const unsigned char*)dones_raw, TB);
    conv_dones_kernel<<<TB / 256, 256>>>(dones_raw, TB);
    pack_weights_kernel<<<(WPK_TOTAL + 255) / 256, 256>>>(
        e1w, e2w, gWi, chw, uhw, uow, v1w, v2w);
    pack_whb_kernel<<<(48 * 512 + 255) / 256, 256>>>(gWh);

    // embed1: relu(obs @ e1w + e1b)
    tgemm_kernel<<<dim3(D / BN, M / BM), blk>>>(M, D, OBS, D, obs, nullptr,
        e1wP, e1wP + 4096, nullptr, nullptr, e1b, emb1, 1, nullptr, nullptr, nullptr);
    // embed2: relu(emb1 @ e2w + e2b)
    tgemm_kernel<<<dim3(D / BN, M / BM), blk>>>(M, D, D, D, emb1, nullptr,
        e2wP, e2wP + 8192, nullptr, nullptr, e2b, emb2, 1, nullptr, nullptr, nullptr);
    // gi = emb2 @ gWi + gbi
    tgemm_kernel<<<dim3(3 * D / BN, M / BM), blk>>>(M, 3 * D, D, 3 * D, emb2, nullptr,
        gWiP, gWiP + 24576, nullptr, nullptr, gbi, gi, 0, nullptr, nullptr, nullptr);
    // sequential GRU scan (tensor-core gemv)
    gru_kernel<<<BATCH / RPB, GTH>>>(gi, dmask, hidden, whb, gbhn, e, out_hidden);

    for (int it = 0; it < ITERS; it++) {
        // [ai | aj] = e @ [W1 | W2]
        tgemm_kernel<<<dim3(2 * CH / BN, M / BM), blk>>>(M, 2 * CH, D, CH, e, nullptr,
            chwP, chwP + 16384, chwP + 8192, chwP + 16384 + 8192,
            nullptr, aiaj, 8, nullptr, nullptr, nullptr);
        couple_ctx_kernel<<<T_STEPS * NE, 256>>>(e, aiaj, chb, cow, cob, ctx);
        // d1 = relu(e @ U1 + ctx @ U2 + uhb)
        tgemm_kernel<<<dim3(D / BN, M / BM), blk>>>(M, D, D, D, e, ctx,
            uhwP, uhwP + 16384, uhwP + 8192, uhwP + 16384 + 8192,
            uhb, d1, 1 | 2, nullptr, nullptr, nullptr);
        // e = (e + relu(d1 @ uow + uob)) * alive   (in place)
        tgemm_kernel<<<dim3(D / BN, M / BM), blk>>>(M, D, D, D, d1, nullptr,
            uowP, uowP + 8192, nullptr, nullptr, uob, e, 4, e, dmask, nullptr);
    }

    // value head: v1 = relu(e@v1w+b); values = relu(v1@v2w+v2b) . vow + vob (fused)
    tgemm_kernel<<<dim3(VH / BN, M / BM), blk>>>(M, VH, D, VH, e, nullptr,
        v1wP, v1wP + 16384, nullptr, nullptr, v1b, v1, 1, nullptr, nullptr, nullptr);
    init_values_kernel<<<TB / 256, 256>>>(out_values, vob);
    tgemm_kernel<<<dim3(VH / BN, M / BM), blk>>>(M, VH, VH, VH, v1, nullptr,
        v2wP, v2wP + 32768, nullptr, nullptr, v2b, out_values, 1 | 16,
        nullptr, nullptr, vow);
}

// round 17
// speedup vs baseline: 1.1472x; 1.0142x over previous
#include <cuda_runtime.h>
#include <cuda_bf16.h>
#include <math.h>

#define T_STEPS 128
#define NE 64
#define NA 8
#define OBS 64
#define D 128
#define CH 128
#define VH 256
#define BATCH 512           // NE*NA
#define TB (T_STEPS*BATCH)  // 65536
#define ITERS 2

// ---------------- scratch (static device arrays: allocation-free) -------------
__device__ float g_emb1[TB * D];
__device__ float g_emb2[TB * D];
__device__ float g_gi[TB * 3 * D];
__device__ float g_e[TB * D];
__device__ float g_aiaj[TB * 2 * CH];
__device__ float g_ctx[TB * D];
__device__ float g_d1[TB * D];
__device__ float g_v1[TB * VH];
__device__ unsigned char g_dmask[TB];
__device__ int g_dflag;
__device__ unsigned g_wpk[253952];       // packed bf16 hi/lo weights (u32)
__device__ unsigned g_whb[2 * 48 * 512]; // GRU Wh as per-thread B fragments (hi|lo)
#define WPK_TOTAL 126976

// ---------------- dones dtype detection + canonicalization --------------------
__global__ void detect_dones_kernel(const unsigned char* __restrict__ p, int n)
{
    __shared__ int s_nonbin, s_off4;
    if (threadIdx.x == 0) { s_nonbin = 0; s_off4 = 0; }
    __syncthreads();
    int nb = 0, o4 = 0;
    for (int i = threadIdx.x; i < n; i += blockDim.x) {
        const unsigned char b = p[i];
        if (b > 1) nb = 1;
        else if (b == 1 && (i & 3)) o4 = 1;
    }
    if (nb) atomicOr(&s_nonbin, 1);
    if (o4) atomicOr(&s_off4, 1);
    __syncthreads();
    if (threadIdx.x == 0)
        g_dflag = s_nonbin ? 1 : (s_off4 ? 0 : 2);
}

__global__ void conv_dones_kernel(const void* __restrict__ p, int n)
{
    const int i = blockIdx.x * blockDim.x + threadIdx.x;
    if (i >= n) return;
    const int f = g_dflag;
    unsigned char m;
    if (f == 1)      m = (((const float*)p)[i] != 0.f);
    else if (f == 2) m = (((const int*)p)[i] != 0);
    else             m = (((const unsigned char*)p)[i] != 0);
    g_dmask[i] = m;
}

// ---------------- bf16 helpers -------------------------------------------------
__device__ __forceinline__ unsigned pack_bf16(float lo_elem, float hi_elem)
{
    unsigned d;
    asm("cvt.rn.bf16x2.f32 %0, %1, %2;" : "=r"(d) : "f"(hi_elem), "f"(lo_elem));
    return d;
}

__device__ __forceinline__ float bf16hi(float x)
{
    return __bfloat162float(__float2bfloat16(x));
}

// ---------------- one-time weight packing --------------------------------------
__global__ void pack_weights_kernel(
    const float* __restrict__ s0, const float* __restrict__ s1,
    const float* __restrict__ s2, const float* __restrict__ s3,
    const float* __restrict__ s4, const float* __restrict__ s5,
    const float* __restrict__ s6, const float* __restrict__ s7)
{
    const int idx = blockIdx.x * blockDim.x + threadIdx.x;
    if (idx >= WPK_TOTAL) return;
    const int cum[9]  = {0, 4096, 12288, 36864, 53248, 69632, 77824, 94208, 126976};
    const int hoff[8] = {0, 8192, 24576, 73728, 106496, 139264, 155648, 188416};
    const int Ns[8]   = {128, 128, 384, 128, 128, 128, 256, 256};
    int m = 0;
#pragma unroll
    for (int q = 0; q < 7; q++) if (idx >= cum[q + 1]) m = q + 1;
    const float* srcs[8] = {s0, s1, s2, s3, s4, s5, s6, s7};
    const int local = idx - cum[m];
    const int N = Ns[m];
    const int kp = local / N;
    const int n  = local - kp * N;
    const float* S = srcs[m];
    const float v0 = S[(size_t)(2 * kp) * N + n];
    const float v1 = S[(size_t)(2 * kp + 1) * N + n];
    const float h0 = bf16hi(v0), h1 = bf16hi(v1);
    const int sz = cum[m + 1] - cum[m];
    g_wpk[hoff[m] + local]      = pack_bf16(h0, h1);
    g_wpk[hoff[m] + sz + local] = pack_bf16(v0 - h0, v1 - h1);
}

// GRU Wh -> per-thread mma B fragments.
__global__ void pack_whb_kernel(const float* __restrict__ Wh)
{
    const int idx = blockIdx.x * blockDim.x + threadIdx.x;
    if (idx >= 48 * 512) return;
    const int i = idx >> 9, t = idx & 511;
    const int kt = i / 6, rem = i % 6, nt = rem >> 1, reg = rem & 1;
    const int w = t >> 5, lane = t & 31, gid = lane >> 2, tig = lane & 3;
    const int n  = w * 24 + nt * 8 + gid;
    const int k0 = kt * 16 + reg * 8 + 2 * tig;
    const float v0 = Wh[(size_t)k0 * 384 + n];
    const float v1 = Wh[(size_t)(k0 + 1) * 384 + n];
    const float h0 = bf16hi(v0), h1 = bf16hi(v1);
    g_whb[idx]            = pack_bf16(h0, h1);
    g_whb[48 * 512 + idx] = pack_bf16(v0 - h0, v1 - h1);
}

// ---------------- init values buffer -------------------------------------------
__global__ void init_values_kernel(float* __restrict__ out, const float* __restrict__ b)
{
    out[blockIdx.x * blockDim.x + threadIdx.x] = b[0];
}

// ---------------- BF16 tensor-core GEMM (pre-packed weights) -------------------
// flags: 1 relu | 2 dual-source | 4 resid+alive | 8 B column-split | 16 fused vout
#define BM 128
#define BN 128
#define BK 16
#define AST 12
#define BST 136

__device__ __forceinline__ void mma_bf16(float* c, const unsigned* a, const unsigned* b)
{
    asm volatile(
        "mma.sync.aligned.m16n8k16.row.col.f32.bf16.bf16.f32 "
        "{%0,%1,%2,%3}, {%4,%5,%6,%7}, {%8,%9}, {%0,%1,%2,%3};"
        : "+f"(c[0]), "+f"(c[1]), "+f"(c[2]), "+f"(c[3])
        : "r"(a[0]), "r"(a[1]), "r"(a[2]), "r"(a[3]), "r"(b[0]), "r"(b[1]));
}

__device__ __forceinline__ void ldsm_x4(unsigned& r0, unsigned& r1, unsigned& r2,
                                        unsigned& r3, unsigned addr)
{
    asm volatile("ldmatrix.sync.aligned.m8n8.x4.shared.b16 {%0,%1,%2,%3}, [%4];"
                 : "=r"(r0), "=r"(r1), "=r"(r2), "=r"(r3) : "r"(addr));
}

__global__ __launch_bounds__(256) void tgemm_kernel(
    int M, int N, int K, int ldb,
    const float* __restrict__ A, const float* __restrict__ A2,
    const unsigned* __restrict__ Bmh, const unsigned* __restrict__ Bml,
    const unsigned* __restrict__ B2h, const unsigned* __restrict__ B2l,
    const float* __restrict__ bias, float* __restrict__ Cout,
    int flags, const float* __restrict__ Ein,
    const unsigned char* __restrict__ dones,
    const float* __restrict__ vw)
{
    __shared__ __align__(16) unsigned As[2][2][BM * AST];
    __shared__ __align__(16) unsigned Bs[2][2][(BK / 2) * BST];

    const int tid  = threadIdx.x;
    const int brow = blockIdx.y * BM;
    const int bcol = blockIdx.x * BN;
    const int w    = tid >> 5, lane = tid & 31;
    const int gid  = lane >> 2, tig = lane & 3;
    const int wm   = (w & 1) * 64;
    const int wn   = (w >> 1) * 32;

    const int arow0 = tid >> 2;
    const int brw   = tid >> 5;
    const int bfc   = (tid & 31) * 4;

    const unsigned aSmemBase = (unsigned)__cvta_generic_to_shared(&As[0][0][0]);
    const unsigned laneOff = ((wm + (lane & 15)) * AST + ((lane & 16) >> 2)) * 4;

    float acc[4][4][4];
#pragma unroll
    for (int i = 0; i < 4; i++)
#pragma unroll
        for (int j = 0; j < 4; j++)
#pragma unroll
            for (int q = 0; q < 4; q++) acc[i][j][q] = 0.f;

    const int nsrc = (flags & 2) ? 2 : 1;
    const int tilesPerSrc = K / BK;
    const int ntiles = nsrc * tilesPerSrc;

    float4 rA[2];
    uint4 rBh, rBl;

    auto loadTile = [&](int t) {
        const int s  = (t >= tilesPerSrc) ? 1 : 0;
        const int k0 = (t - s * tilesPerSrc) * BK;
        const float* Ap = s ? A2 : A;
        const unsigned *Bph, *Bpl;
        int bc;
        if (flags & 8) {
            const bool hi = (bcol >= BN);
            Bph = hi ? B2h : Bmh;  Bpl = hi ? B2l : Bml;  bc = 0;
        } else {
            Bph = s ? B2h : Bmh;   Bpl = s ? B2l : Bml;   bc = bcol;
        }
        const int afc = (tid & 3) * 4;
        rA[0] = *(const float4*)(Ap + (size_t)(brow + arow0) * K + k0 + afc);
        rA[1] = *(const float4*)(Ap + (size_t)(brow + arow0 + 64) * K + k0 + afc);
        const size_t boff = (size_t)(k0 / 2 + brw) * ldb + bc + bfc;
        rBh = *(const uint4*)(Bph + boff);
        rBl = *(const uint4*)(Bpl + boff);
    };

    auto storeTile = [&](int buf) {
#pragma unroll
        for (int p = 0; p < 2; p++) {
            const float4 v = rA[p];
            const float h0 = bf16hi(v.x), h1 = bf16hi(v.y);
            const float h2 = bf16hi(v.z), h3 = bf16hi(v.w);
            const int base = (arow0 + p * 64) * AST + (tid & 3) * 2;
            *(uint2*)&As[buf][0][base] = make_uint2(pack_bf16(h0, h1), pack_bf16(h2, h3));
            *(uint2*)&As[buf][1][base] = make_uint2(pack_bf16(v.x - h0, v.y - h1),
                                                    pack_bf16(v.z - h2, v.w - h3));
        }
        const int base = brw * BST + bfc;
        *(uint4*)&Bs[buf][0][base] = rBh;
        *(uint4*)&Bs[buf][1][base] = rBl;
    };

    loadTile(0);
    storeTile(0);
    __syncthreads();

    for (int t = 0; t < ntiles; t++) {
        if (t + 1 < ntiles) loadTile(t + 1);

        const int cur = t & 1;
        const unsigned* Bsh = Bs[cur][0];
        const unsigned* Bsl = Bs[cur][1];
        const unsigned aTileH = aSmemBase + (unsigned)(cur * (2 * BM * AST * 4)) + laneOff;
        const unsigned aTileL = aTileH + (unsigned)(BM * AST * 4);

        unsigned bh[4][2], bl[4][2];
#pragma unroll
        for (int ns = 0; ns < 4; ns++) {
            const int n = wn + ns * 8 + gid;
            bh[ns][0] = Bsh[tig * BST + n];
            bh[ns][1] = Bsh[(tig + 4) * BST + n];
            bl[ns][0] = Bsl[tig * BST + n];
            bl[ns][1] = Bsl[(tig + 4) * BST + n];
        }
#pragma unroll
        for (int ms = 0; ms < 4; ms++) {
            unsigned ah[4], al[4];
            ldsm_x4(ah[0], ah[1], ah[2], ah[3], aTileH + (unsigned)(ms * 16 * AST * 4));
            ldsm_x4(al[0], al[1], al[2], al[3], aTileL + (unsigned)(ms * 16 * AST * 4));
#pragma unroll
            for (int ns = 0; ns < 4; ns++) {
                mma_bf16(acc[ms][ns], ah, bh[ns]);
                mma_bf16(acc[ms][ns], ah, bl[ns]);
                mma_bf16(acc[ms][ns], al, bh[ns]);
            }
        }

        if (t + 1 < ntiles) {
            storeTile((t + 1) & 1);
            __syncthreads();
        }
    }

    // ---- fused value epilogue ----
    if (flags & 16) {
#pragma unroll
        for (int ms = 0; ms < 4; ms++) {
            const int r0 = brow + wm + ms * 16 + gid;
            float p0 = 0.f, p1 = 0.f;
#pragma unroll
            for (int ns = 0; ns < 4; ns++) {
                const int c = bcol + wn + ns * 8 + tig * 2;
                const float b0 = bias[c], b1 = bias[c + 1];
                const float w0 = vw[c],  w1 = vw[c + 1];
                p0 += fmaxf(acc[ms][ns][0] + b0, 0.f) * w0
                    + fmaxf(acc[ms][ns][1] + b1, 0.f) * w1;
                p1 += fmaxf(acc[ms][ns][2] + b0, 0.f) * w0
                    + fmaxf(acc[ms][ns][3] + b1, 0.f) * w1;
            }
            p0 += __shfl_xor_sync(0xffffffffu, p0, 1);
            p0 += __shfl_xor_sync(0xffffffffu, p0, 2);
            p1 += __shfl_xor_sync(0xffffffffu, p1, 1);
            p1 += __shfl_xor_sync(0xffffffffu, p1, 2);
            if (tig == 0) {
                atomicAdd(&Cout[r0], p0);
                atomicAdd(&Cout[r0 + 8], p1);
            }
        }
        return;
    }

    const bool hasb   = (bias != nullptr);
    const bool resid  = (flags & 4);
    const bool dorelu = (flags & 5);
#pragma unroll
    for (int ms = 0; ms < 4; ms++) {
        const int r0 = brow + wm + ms * 16 + gid;
        const int r1 = r0 + 8;
        float alive0 = 1.f, alive1 = 1.f;
        const float *E0 = nullptr, *E1 = nullptr;
        if (resid) {
            alive0 = dones[r0] ? 0.f : 1.f;
            alive1 = dones[r1] ? 0.f : 1.f;
            E0 = Ein + (size_t)r0 * N;
            E1 = Ein + (size_t)r1 * N;
        }
#pragma unroll
        for (int ns = 0; ns < 4; ns++) {
            const int c = bcol + wn + ns * 8 + tig * 2;
            float b0 = 0.f, b1 = 0.f;
            if (hasb) { b0 = bias[c]; b1 = bias[c + 1]; }
            float v0 = acc[ms][ns][0] + b0;
            float v1 = acc[ms][ns][1] + b1;
            float v2 = acc[ms][ns][2] + b0;
            float v3 = acc[ms][ns][3] + b1;
            if (dorelu) {
                v0 = fmaxf(v0, 0.f); v1 = fmaxf(v1, 0.f);
                v2 = fmaxf(v2, 0.f); v3 = fmaxf(v3, 0.f);
            }
            if (resid) {
                v0 = (E0[c] + v0) * alive0;     v1 = (E0[c + 1] + v1) * alive0;
                v2 = (E1[c] + v2) * alive1;     v3 = (E1[c + 1] + v3) * alive1;
            }
            *(float2*)&Cout[(size_t)r0 * N + c] = make_float2(v0, v1);
            *(float2*)&Cout[(size_t)r1 * N + c] = make_float2(v2, v3);
        }
    }
}

// ---------------- GRU scan v5: tc gemv, bl in smem, split acc chain ------------
// 128 blocks x 4 rows; 512 threads = 16 warps x 24 gh columns.
// bh (48 u32) in registers; bl as 24 uint2/thread in dynamic smem [pair][tid].
// kt-even/odd accumulate into separate acc sets -> mma dep chain 24 -> 12.
#define RPB 4
#define GTH 512
#define GRU_DSM (24 * 512 * 8)   // 98304 B dynamic smem for bl pairs

__device__ __forceinline__ float sig_fast(float x)
{
    return __fdividef(1.f, 1.f + __expf(-x));
}
__device__ __forceinline__ float tanh_fast(float x)
{
    return __fdividef(2.f, 1.f + __expf(-2.f * x)) - 1.f;
}

__global__ __launch_bounds__(GTH, 1) void gru_kernel(
    const float* __restrict__ gi,            // (T,B,3D)
    const unsigned char* __restrict__ dones, // (T,B)
    const float* __restrict__ h0,            // (B,D)
    const unsigned* __restrict__ whb,        // packed Wh B-fragments
    const float* __restrict__ bhn,
    float* __restrict__ e_out,               // (T,B,D)
    float* __restrict__ hidden_out)          // (B,D)
{
    extern __shared__ __align__(16) uint2 sBl[];          // [24][512]
    __shared__ __align__(16) unsigned sA[2 * 16 * 68];    // A-tile hi | lo (stride 68)
    __shared__ float hs[RPB * 132];
    __shared__ float ghs[RPB * 388];
    __shared__ float sbhn[D];
    __shared__ unsigned char sdn[T_STEPS * RPB];

    const int tid = threadIdx.x;
    const int rowbase = blockIdx.x * RPB;
    const int w = tid >> 5, lane = tid & 31;
    const int gid = lane >> 2, tig = lane & 3;

    // bh fragments -> registers; bl -> smem pairs [p][tid]
    unsigned bh[48];
#pragma unroll
    for (int i = 0; i < 48; i++)
        bh[i] = whb[i * 512 + tid];
#pragma unroll
    for (int p = 0; p < 24; p++)
        sBl[p * 512 + tid] = make_uint2(whb[48 * 512 + (2 * p) * 512 + tid],
                                        whb[48 * 512 + (2 * p + 1) * 512 + tid]);

    if (tid < D) sbhn[tid] = bhn[tid];
    if (tid < T_STEPS)
        *(uchar4*)&sdn[tid * 4] = *(const uchar4*)&dones[tid * BATCH + rowbase];
    // zero pad rows 4..15 of A-tile (hi + lo)
    for (int i = tid; i < 12 * 68; i += GTH) {
        const int rr = 4 + i / 68, cc = i % 68;
        sA[rr * 68 + cc] = 0u;
        sA[16 * 68 + rr * 68 + cc] = 0u;
    }

    const int r = tid >> 7, d = tid & 127;
    const int row = rowbase + r;

    float pa0, pa1, pa2;
    auto prefetch = [&](int t) {
        const size_t gib = ((size_t)t * BATCH + row) * (3 * D);
        pa0 = gi[gib + d];
        pa1 = gi[gib + D + d];
        pa2 = gi[gib + 2 * D + d];
    };
    prefetch(0);
    __syncthreads();

    // init h (dones[0] reset)
    {
        const float v = sdn[r] ? 0.f : h0[(size_t)row * D + d];
        hs[r * 132 + d] = v;
        const float vo = __shfl_down_sync(0xffffffffu, v, 1);
        if (!(d & 1)) {
            const float h0p = bf16hi(v), h1p = bf16hi(vo);
            sA[r * 68 + (d >> 1)] = pack_bf16(h0p, h1p);
            sA[16 * 68 + r * 68 + (d >> 1)] = pack_bf16(v - h0p, vo - h1p);
        }
    }
    __syncthreads();

    const unsigned smA = (unsigned)__cvta_generic_to_shared(sA);
    const unsigned aOffBase = smA + ((lane & 15) * 68 + ((lane & 16) >> 2)) * 4;

    for (int t = 0; t < T_STEPS; t++) {
        // gemv via mma; kt parity split halves the acc dependency chain
        float acc[2][3][4];
#pragma unroll
        for (int par = 0; par < 2; par++)
#pragma unroll
            for (int nt = 0; nt < 3; nt++)
#pragma unroll
                for (int q = 0; q < 4; q++) acc[par][nt][q] = 0.f;

#pragma unroll
        for (int kt = 0; kt < 8; kt++) {
            unsigned ah[4], al[4];
            ldsm_x4(ah[0], ah[1], ah[2], ah[3], aOffBase + (unsigned)(kt * 8 * 4));
            ldsm_x4(al[0], al[1], al[2], al[3], aOffBase + (unsigned)((16 * 68 + kt * 8) * 4));
            const int par = kt & 1;
#pragma unroll
            for (int nt = 0; nt < 3; nt++) {
                const uint2 blp = sBl[(kt * 3 + nt) * 512 + tid];
                const unsigned blr[2] = {blp.x, blp.y};
                mma_bf16(acc[par][nt], ah, &bh[kt * 6 + nt * 2]);
                mma_bf16(acc[par][nt], ah, blr);
                mma_bf16(acc[par][nt], al, &bh[kt * 6 + nt * 2]);
            }
        }
        if (gid < 4) {
#pragma unroll
            for (int nt = 0; nt < 3; nt++) {
                const int n = w * 24 + nt * 8 + tig * 2;
                *(float2*)&ghs[gid * 388 + n] =
                    make_float2(acc[0][nt][0] + acc[1][nt][0],
                                acc[0][nt][1] + acc[1][nt][1]);
            }
        }
        __syncthreads();

        // gates: 1 item per thread
        {
            const float h_r = ghs[r * 388 + d];
            const float h_z = ghs[r * 388 + 128 + d];
            const float h_n = ghs[r * 388 + 256 + d];
            const float hprev = hs[r * 132 + d];
            const float rg = sig_fast(pa0 + h_r);
            const float zg = sig_fast(pa1 + h_z);
            const float ng = tanh_fast(pa2 + rg * (h_n + sbhn[d]));
            const float hn = (1.f - zg) * ng + zg * hprev;
            const float alive = sdn[t * 4 + r] ? 0.f : 1.f;
            e_out[((size_t)t * BATCH + row) * D + d] = hn * alive;
            if (t == T_STEPS - 1) {
                hidden_out[(size_t)row * D + d] = hn;
            } else {
                const float hv = sdn[(t + 1) * 4 + r] ? 0.f : hn;
                hs[r * 132 + d] = hv;
                const float hvo = __shfl_down_sync(0xffffffffu, hv, 1);
                if (!(d & 1)) {
                    const float h0p = bf16hi(hv), h1p = bf16hi(hvo);
                    sA[r * 68 + (d >> 1)] = pack_bf16(h0p, h1p);
                    sA[16 * 68 + r * 68 + (d >> 1)] = pack_bf16(hv - h0p, hvo - h1p);
                }
            }
        }
        if (t + 1 < T_STEPS) prefetch(t + 1);
        __syncthreads();
    }
}

// ---------------- fused pairwise-coupling C + context (lane-parallel j) --------
__global__ __launch_bounds__(256) void couple_ctx_kernel(
    const float* __restrict__ e, const float* __restrict__ aiaj,
    const float* __restrict__ chb,
    const float* __restrict__ cow, const float* __restrict__ cob,
    float* __restrict__ ctx)
{
    __shared__ float sai[NA * 132];
    __shared__ float sajt[128 * 9];
    __shared__ float se[NA * D];
    __shared__ float sb[CH], sw[CH];
    __shared__ float sC[NA * NA];

    const int g  = blockIdx.x;
    const size_t base  = (size_t)g * NA * D;
    const size_t base2 = (size_t)g * NA * 256;
    const int tid = threadIdx.x;
    const int lane = tid & 31, warp = tid >> 5;

    {
        const int j = warp;
        const int k0 = lane * 4;
        const float4 vi = *(const float4*)&aiaj[base2 + j * 256 + k0];
        const float4 vj = *(const float4*)&aiaj[base2 + j * 256 + 128 + k0];
        *(float4*)&sai[j * 132 + k0] = vi;
        sajt[(k0 + 0) * 9 + j] = vj.x;
        sajt[(k0 + 1) * 9 + j] = vj.y;
        sajt[(k0 + 2) * 9 + j] = vj.z;
        sajt[(k0 + 3) * 9 + j] = vj.w;
    }
    *(float4*)&se[tid * 4] = *(const float4*)&e[base + tid * 4];
    if (tid < CH) { sb[tid] = chb[tid]; sw[tid] = cow[tid]; }
    __syncthreads();

    {
        const int i = warp;
        const int jj = lane & 7, slice = lane >> 3;
        const float cb = cob[0];
        float s = 0.f;
#pragma unroll
        for (int it = 0; it < 32; it++) {
            const int kk = slice * 32 + ((it + slice * 8) & 31);
            const float v = sai[i * 132 + kk] + sajt[kk * 9 + jj] + sb[kk];
            s += fmaxf(v, 0.f) * sw[kk];
        }
        s += __shfl_xor_sync(0xffffffffu, s, 8);
        s += __shfl_xor_sync(0xffffffffu, s, 16);
        if (lane < 8)
            sC[i * NA + lane] = (i == lane) ? 0.f : 1.f / (1.f + expf(-(s + cb)));
    }
    __syncthreads();

    for (int idx = tid; idx < NA * D; idx += 256) {
        const int i = idx >> 7, d = idx & 127;
        float s = 0.f;
#pragma unroll
        for (int j = 0; j < NA; j++) s += sC[i * NA + j] * se[j * D + d];
        ctx[base + idx] = s;
    }
}

// ---------------- launcher -------------------------------------------------------
extern "C" void kernel_launch(void* const* d_in, const int* in_sizes, int n_in,
                              void* d_out, int out_size)
{
    const float* hidden = (const float*)d_in[0];
    const float* obs    = (const float*)d_in[1];
    const void*  dones_raw = d_in[2];
    const float* e1w = (const float*)d_in[3];
    const float* e1b = (const float*)d_in[4];
    const float* e2w = (const float*)d_in[5];
    const float* e2b = (const float*)d_in[6];
    const float* gWi = (const float*)d_in[7];
    const float* gbi = (const float*)d_in[8];
    const float* gWh = (const float*)d_in[9];
    const float* gbhn = (const float*)d_in[10];
    const float* chw = (const float*)d_in[11];
    const float* chb = (const float*)d_in[12];
    const float* cow = (const float*)d_in[13];
    const float* cob = (const float*)d_in[14];
    const float* uhw = (const float*)d_in[15];
    const float* uhb = (const float*)d_in[16];
    const float* uow = (const float*)d_in[17];
    const float* uob = (const float*)d_in[18];
    const float* v1w = (const float*)d_in[19];
    const float* v1b = (const float*)d_in[20];
    const float* v2w = (const float*)d_in[21];
    const float* v2b = (const float*)d_in[22];
    const float* vow = (const float*)d_in[23];
    const float* vob = (const float*)d_in[24];

    float* out_hidden = (float*)d_out;                 // (B, D)
    float* out_values = (float*)d_out + BATCH * D;     // (T, B)

    float *emb1, *emb2, *gi, *e, *aiaj, *ctx, *d1, *v1;
    unsigned char* dmask;
    unsigned *wpk, *whb;
    cudaGetSymbolAddress((void**)&emb1, g_emb1);
    cudaGetSymbolAddress((void**)&emb2, g_emb2);
    cudaGetSymbolAddress((void**)&gi,   g_gi);
    cudaGetSymbolAddress((void**)&e,    g_e);
    cudaGetSymbolAddress((void**)&aiaj, g_aiaj);
    cudaGetSymbolAddress((void**)&ctx,  g_ctx);
    cudaGetSymbolAddress((void**)&d1,   g_d1);
    cudaGetSymbolAddress((void**)&v1,   g_v1);
    cudaGetSymbolAddress((void**)&dmask, g_dmask);
    cudaGetSymbolAddress((void**)&wpk,  g_wpk);
    cudaGetSymbolAddress((void**)&whb,  g_whb);

    unsigned* e1wP = wpk + 0;        // sz 4096
    unsigned* e2wP = wpk + 8192;     // sz 8192
    unsigned* gWiP = wpk + 24576;    // sz 24576
    unsigned* chwP = wpk + 73728;    // sz 16384
    unsigned* uhwP = wpk + 106496;   // sz 16384
    unsigned* uowP = wpk + 139264;   // sz 8192
    unsigned* v1wP = wpk + 155648;   // sz 16384
    unsigned* v2wP = wpk + 188416;   // sz 32768

    cudaFuncSetAttribute(gru_kernel, cudaFuncAttributeMaxDynamicSharedMemorySize, GRU_DSM);

    const int M = TB;
    const dim3 blk(256);

    detect_dones_kernel<<<1, 256>>>((const unsigned char*)dones_raw, TB);
    conv_dones_kernel<<<TB / 256, 256>>>(dones_raw, TB);
    pack_weights_kernel<<<(WPK_TOTAL + 255) / 256, 256>>>(
        e1w, e2w, gWi, chw, uhw, uow, v1w, v2w);
    pack_whb_kernel<<<(48 * 512 + 255) / 256, 256>>>(gWh);
    init_values_kernel<<<TB / 256, 256>>>(out_values, vob);   // early: no deps

    // embed1: relu(obs @ e1w + e1b)
    tgemm_kernel<<<dim3(D / BN, M / BM), blk>>>(M, D, OBS, D, obs, nullptr,
        e1wP, e1wP + 4096, nullptr, nullptr, e1b, emb1, 1, nullptr, nullptr, nullptr);
    // embed2: relu(emb1 @ e2w + e2b)
    tgemm_kernel<<<dim3(D / BN, M / BM), blk>>>(M, D, D, D, emb1, nullptr,
        e2wP, e2wP + 8192, nullptr, nullptr, e2b, emb2, 1, nullptr, nullptr, nullptr);
    // gi = emb2 @ gWi + gbi
    tgemm_kernel<<<dim3(3 * D / BN, M / BM), blk>>>(M, 3 * D, D, 3 * D, emb2, nullptr,
        gWiP, gWiP + 24576, nullptr, nullptr, gbi, gi, 0, nullptr, nullptr, nullptr);
    // sequential GRU scan (tensor-core gemv, split chain)
    gru_kernel<<<BATCH / RPB, GTH, GRU_DSM>>>(gi, dmask, hidden, whb, gbhn, e, out_hidden);

    for (int it = 0; it < ITERS; it++) {
        // [ai | aj] = e @ [W1 | W2]
        tgemm_kernel<<<dim3(2 * CH / BN, M / BM), blk>>>(M, 2 * CH, D, CH, e, nullptr,
            chwP, chwP + 16384, chwP + 8192, chwP + 16384 + 8192,
            nullptr, aiaj, 8, nullptr, nullptr, nullptr);
        couple_ctx_kernel<<<T_STEPS * NE, 256>>>(e, aiaj, chb, cow, cob, ctx);
        // d1 = relu(e @ U1 + ctx @ U2 + uhb)
        tgemm_kernel<<<dim3(D / BN, M / BM), blk>>>(M, D, D, D, e, ctx,
            uhwP, uhwP + 16384, uhwP + 8192, uhwP + 16384 + 8192,
            uhb, d1, 1 | 2, nullptr, nullptr, nullptr);
        // e = (e + relu(d1 @ uow + uob)) * alive   (in place)
        tgemm_kernel<<<dim3(D / BN, M / BM), blk>>>(M, D, D, D, d1, nullptr,
            uowP, uowP + 8192, nullptr, nullptr, uob, e, 4, e, dmask, nullptr);
    }

    // value head: v1 = relu(e@v1w+b); values += relu(v1@v2w+v2b) . vow (fused)
    tgemm_kernel<<<dim3(VH / BN, M / BM), blk>>>(M, VH, D, VH, e, nullptr,
        v1wP, v1wP + 16384, nullptr, nullptr, v1b, v1, 1, nullptr, nullptr, nullptr);
    tgemm_kernel<<<dim3(VH / BN, M / BM), blk>>>(M, VH, VH, VH, v1, nullptr,
        v2wP, v2wP + 32768, nullptr, nullptr, v2b, out_values, 1 | 16,
        nullptr, nullptr, vow);
}